// round 1
// baseline (speedup 1.0000x reference)
#include <cuda_runtime.h>
#include <cuda_bf16.h>
#include <math.h>

#define NN 8192
#define DD 128
#define BLK 128
#define PAD 4
#define LDA (BLK + PAD)   // 132 floats per smem row
#define SMEM_BYTES (2 * 128 * LDA * 4)

// scratch (statically allocated; no runtime allocation)
__device__ float g_logits[(size_t)NN * NN];   // 268 MB
__device__ float g_neg[NN];
__device__ float g_rowloss[NN];

// ---------------------------------------------------------------------------
// Kernel 1: fused SGEMM. l_ij = 10 * dot(f_i, f_j). Stores logits, accumulates
// Neg_i = sum_{lab_j != lab_i} exp(l_ij - 10).
// Grid: (64 i-tiles, 4 j-chunks). Block: 256 threads, 8x8 microtile.
// ---------------------------------------------------------------------------
__global__ __launch_bounds__(256, 1)
void k1_gemm_neg(const float* __restrict__ feats, const int* __restrict__ labels)
{
    extern __shared__ float smem[];
    float* As = smem;               // As[k][m], transposed
    float* Bs = smem + 128 * LDA;   // Bs[k][n], transposed
    __shared__ int labI[BLK];
    __shared__ int labJ[BLK];

    const int tid = threadIdx.x;
    const int tx = tid & 15;        // 0..15 -> n block
    const int ty = tid >> 4;        // 0..15 -> m block
    const int iBase = blockIdx.x * BLK;
    const int jChunk = blockIdx.y * (NN / 4);

    // Load A tile (128 rows x 128 k), transposed into smem
    for (int idx = tid; idx < BLK * 32; idx += 256) {
        int row = idx >> 5;
        int c4 = (idx & 31) * 4;
        float4 v = *(const float4*)(feats + (size_t)(iBase + row) * DD + c4);
        As[(c4 + 0) * LDA + row] = v.x;
        As[(c4 + 1) * LDA + row] = v.y;
        As[(c4 + 2) * LDA + row] = v.z;
        As[(c4 + 3) * LDA + row] = v.w;
    }
    if (tid < BLK) labI[tid] = labels[iBase + tid];
    __syncthreads();

    int myLab[8];
#pragma unroll
    for (int u = 0; u < 8; u++) myLab[u] = labI[ty * 8 + u];

    float negAcc[8];
#pragma unroll
    for (int u = 0; u < 8; u++) negAcc[u] = 0.0f;

    const int numJT = (NN / 4) / BLK;  // 16
    for (int jt = 0; jt < numJT; jt++) {
        const int jBase = jChunk + jt * BLK;

        __syncthreads();  // protect Bs/labJ from previous-iter readers
        for (int idx = tid; idx < BLK * 32; idx += 256) {
            int row = idx >> 5;
            int c4 = (idx & 31) * 4;
            float4 v = *(const float4*)(feats + (size_t)(jBase + row) * DD + c4);
            Bs[(c4 + 0) * LDA + row] = v.x;
            Bs[(c4 + 1) * LDA + row] = v.y;
            Bs[(c4 + 2) * LDA + row] = v.z;
            Bs[(c4 + 3) * LDA + row] = v.w;
        }
        if (tid < BLK) labJ[tid] = labels[jBase + tid];
        __syncthreads();

        float acc[8][8];
#pragma unroll
        for (int u = 0; u < 8; u++)
#pragma unroll
            for (int v = 0; v < 8; v++) acc[u][v] = 0.0f;

#pragma unroll 4
        for (int k = 0; k < 128; k++) {
            float4 a0 = *(const float4*)&As[k * LDA + ty * 8];
            float4 a1 = *(const float4*)&As[k * LDA + ty * 8 + 4];
            float4 b0 = *(const float4*)&Bs[k * LDA + tx * 8];
            float4 b1 = *(const float4*)&Bs[k * LDA + tx * 8 + 4];
            float af[8] = {a0.x, a0.y, a0.z, a0.w, a1.x, a1.y, a1.z, a1.w};
            float bf[8] = {b0.x, b0.y, b0.z, b0.w, b1.x, b1.y, b1.z, b1.w};
#pragma unroll
            for (int u = 0; u < 8; u++)
#pragma unroll
                for (int v = 0; v < 8; v++) acc[u][v] += af[u] * bf[v];
        }

        // Epilogue: logits store + Neg accumulation
#pragma unroll
        for (int u = 0; u < 8; u++) {
            const size_t gi = (size_t)(iBase + ty * 8 + u);
            float lv[8];
#pragma unroll
            for (int v = 0; v < 8; v++) {
                float l = acc[u][v] * 10.0f;   // 1/TEMPERATURE
                lv[v] = l;
                float e = __expf(l - 10.0f);
                if (labJ[tx * 8 + v] != myLab[u]) negAcc[u] += e;
            }
            float4* dst = (float4*)(g_logits + gi * NN + jBase + tx * 8);
            dst[0] = make_float4(lv[0], lv[1], lv[2], lv[3]);
            dst[1] = make_float4(lv[4], lv[5], lv[6], lv[7]);
        }
    }

    // Reduce negAcc across the 16 tx lanes (xor net stays within 16-lane half)
#pragma unroll
    for (int u = 0; u < 8; u++) {
        float v = negAcc[u];
#pragma unroll
        for (int off = 1; off < 16; off <<= 1)
            v += __shfl_xor_sync(0xffffffffu, v, off);
        if (tx == 0) atomicAdd(&g_neg[iBase + ty * 8 + u], v);
    }
}

// ---------------------------------------------------------------------------
// Kernel 2: per-row pass. S_i = sum_pos [ d - log(exp(d) + Neg_i) ], d = l - 10
// One CTA per row.
// ---------------------------------------------------------------------------
__global__ __launch_bounds__(256)
void k2_rowloss(const int* __restrict__ labels)
{
    const int i = blockIdx.x;
    const int tid = threadIdx.x;
    const int myLab = labels[i];
    const float neg = g_neg[i];
    const float* __restrict__ row = g_logits + (size_t)i * NN;

    float S = 0.0f;
    int cnt = 0;
    for (int j = tid; j < NN; j += 256) {
        float l = row[j];
        if (j != i && labels[j] == myLab) {
            float d = l - 10.0f;
            S += d - __logf(__expf(d) + neg);
            cnt++;
        }
    }

    // block reduce
    __shared__ float sS[256];
    __shared__ int sC[256];
    sS[tid] = S;
    sC[tid] = cnt;
    __syncthreads();
    for (int s = 128; s > 0; s >>= 1) {
        if (tid < s) { sS[tid] += sS[tid + s]; sC[tid] += sC[tid + s]; }
        __syncthreads();
    }
    if (tid == 0) {
        float mean_log_prob_pos = sS[0] / (float)sC[0];
        g_rowloss[i] = -(0.1f / 0.07f) * mean_log_prob_pos;
    }
}

// ---------------------------------------------------------------------------
// Kernel 3: deterministic final mean over rows.
// ---------------------------------------------------------------------------
__global__ __launch_bounds__(256)
void k3_mean(float* __restrict__ out)
{
    const int tid = threadIdx.x;
    float s = 0.0f;
    for (int i = tid; i < NN; i += 256) s += g_rowloss[i];
    __shared__ float sS[256];
    sS[tid] = s;
    __syncthreads();
    for (int k = 128; k > 0; k >>= 1) {
        if (tid < k) sS[tid] += sS[tid + k];
        __syncthreads();
    }
    if (tid == 0) out[0] = sS[0] / (float)NN;
}

// ---------------------------------------------------------------------------
extern "C" void kernel_launch(void* const* d_in, const int* in_sizes, int n_in,
                              void* d_out, int out_size)
{
    const float* feats = (const float*)d_in[0];
    const int* labels = (const int*)d_in[1];
    float* out = (float*)d_out;

    void* negp = nullptr;
    cudaGetSymbolAddress(&negp, g_neg);
    cudaMemsetAsync(negp, 0, NN * sizeof(float));

    cudaFuncSetAttribute(k1_gemm_neg,
                         cudaFuncAttributeMaxDynamicSharedMemorySize, SMEM_BYTES);

    dim3 grid1(NN / BLK, 4);  // 64 i-tiles x 4 j-chunks
    k1_gemm_neg<<<grid1, 256, SMEM_BYTES>>>(feats, labels);
    k2_rowloss<<<NN, 256>>>(labels);
    k3_mean<<<1, 256>>>(out);
}

// round 4
// speedup vs baseline: 1.0229x; 1.0229x over previous
#include <cuda_runtime.h>
#include <cuda_bf16.h>
#include <cstdint>
#include <math.h>

#define NN 8192
#define DD 128

// tcgen05 is an arch-specific ('a') feature: only emit it on the sm_103a /
// sm_100a compilation paths. The plain compute_103 path gets empty kernel
// bodies; at runtime the exact-match sm_103a cubin is selected.
#if defined(__CUDA_ARCH__) && \
    (defined(__CUDA_ARCH_FEAT_SM103_ALL) || defined(__CUDA_ARCH_FEAT_SM100_ALL) || \
     defined(__CUDA_ARCH_SPECIFIC__) || defined(__CUDA_ARCH_FAMILY_SPECIFIC__))
#define HAS_TCGEN05 1
#else
#define HAS_TCGEN05 0
#endif

// ---------------- scratch (static device memory; no runtime alloc) ----------
__device__ __nv_bfloat16 g_hi[(size_t)NN * DD];
__device__ __nv_bfloat16 g_lo[(size_t)NN * DD];
__device__ float g_neg[NN];
__device__ float g_posd[NN];
__device__ float g_cnt[NN];
__device__ float g_T[NN];

// ---------------- SMEM layout ----------------------------------------------
#define OFF_TMEM 0
#define OFF_MBAR 8
#define OFF_LABJ 16        // 128 ints
#define SM_AHI 1024
#define SM_ALO (SM_AHI + 32768)
#define SM_BHI (SM_ALO + 32768)
#define SM_BLO (SM_BHI + 32768)
#define SM_TOTAL (SM_BLO + 32768)

#if HAS_TCGEN05
// ---------------- PTX helpers ----------------------------------------------
__device__ __forceinline__ uint32_t smem_u32(const void* p) {
    uint32_t a;
    asm("{ .reg .u64 t; cvta.to.shared.u64 t, %1; cvt.u32.u64 %0, t; }" : "=r"(a) : "l"(p));
    return a;
}

#define TCG_ALLOC(sm, n) asm volatile("tcgen05.alloc.cta_group::1.sync.aligned.shared::cta.b32 [%0], %1;" :: "r"(sm), "r"(n) : "memory")
#define TCG_DEALLOC(t, n) asm volatile("tcgen05.dealloc.cta_group::1.sync.aligned.b32 %0, %1;" :: "r"(t), "r"(n))
#define TCG_RELINQ() asm volatile("tcgen05.relinquish_alloc_permit.cta_group::1.sync.aligned;")
#define TCG_COMMIT(mb) asm volatile("tcgen05.commit.cta_group::1.mbarrier::arrive::one.shared::cluster.b64 [%0];" :: "r"(mb) : "memory")
#define TCG_WAIT_LD() asm volatile("tcgen05.wait::ld.sync.aligned;" ::: "memory")
#define TCG_FENCE_BEFORE() asm volatile("tcgen05.fence::before_thread_sync;" ::: "memory")
#define TCG_FENCE_AFTER() asm volatile("tcgen05.fence::after_thread_sync;" ::: "memory")
#define FENCE_ASYNC_SHARED() asm volatile("fence.proxy.async.shared::cta;" ::: "memory")
#define MBAR_INIT(mb, c) asm volatile("mbarrier.init.shared.b64 [%0], %1;" :: "r"(mb), "r"(c) : "memory")
#define MBAR_INVAL(mb) asm volatile("mbarrier.inval.shared.b64 [%0];" :: "r"(mb) : "memory")

#define MBAR_WAIT(mb, ph) do { \
    uint32_t _m = (mb); uint32_t _p = (ph); uint32_t _d; \
    asm volatile("{ .reg .pred p; mbarrier.try_wait.parity.acquire.cta.shared::cta.b64 p, [%1], %2; selp.b32 %0,1,0,p; }" \
                 : "=r"(_d) : "r"(_m), "r"(_p) : "memory"); \
    if (!_d) { \
        asm volatile("{ .reg .pred P1; WL_%=: mbarrier.try_wait.parity.acquire.cta.shared::cta.b64 P1, [%0], %1, 0x989680; @P1 bra.uni WD_%=; bra.uni WL_%=; WD_%=: }" \
                     :: "r"(_m), "r"(_p) : "memory"); \
    } } while (0)

#define LDTM_X32(r, addr) \
    asm volatile("tcgen05.ld.sync.aligned.32x32b.x32.b32 " \
        "{%0,%1,%2,%3,%4,%5,%6,%7,%8,%9,%10,%11,%12,%13,%14,%15," \
        "%16,%17,%18,%19,%20,%21,%22,%23,%24,%25,%26,%27,%28,%29,%30,%31}, [%32];" \
        : "=r"((r)[0]),"=r"((r)[1]),"=r"((r)[2]),"=r"((r)[3]),"=r"((r)[4]),"=r"((r)[5]),"=r"((r)[6]),"=r"((r)[7]), \
          "=r"((r)[8]),"=r"((r)[9]),"=r"((r)[10]),"=r"((r)[11]),"=r"((r)[12]),"=r"((r)[13]),"=r"((r)[14]),"=r"((r)[15]), \
          "=r"((r)[16]),"=r"((r)[17]),"=r"((r)[18]),"=r"((r)[19]),"=r"((r)[20]),"=r"((r)[21]),"=r"((r)[22]),"=r"((r)[23]), \
          "=r"((r)[24]),"=r"((r)[25]),"=r"((r)[26]),"=r"((r)[27]),"=r"((r)[28]),"=r"((r)[29]),"=r"((r)[30]),"=r"((r)[31]) \
        : "r"(addr))

__device__ __forceinline__ void mma_f16_ss(uint32_t d, uint64_t a, uint64_t b,
                                           uint32_t idesc, uint32_t en) {
    asm volatile(
        "{\n\t.reg .pred p;\n\t"
        "setp.ne.u32 p, %5, 0;\n\t"
        "tcgen05.mma.cta_group::1.kind::f16 [%0], %1, %2, %3, {%4,%4,%4,%4}, p;\n\t}"
        :: "r"(d), "l"(a), "l"(b), "r"(idesc), "r"(0u), "r"(en) : "memory");
}

// SW128 K-major descriptor base: layout=SW128, version=1, SBO=64, LBO=1
static constexpr uint64_t DESC_BASE =
    (uint64_t(2) << 61) | (uint64_t(1) << 46) | (uint64_t(64) << 32) | (uint64_t(1) << 16);

// idesc: D=F32, A=BF16, B=BF16, N=128, M=128 (K-major both)
static constexpr uint32_t IDESC =
    (1u << 4) | (1u << 7) | (1u << 10) | ((128u / 8) << 17) | ((128u / 16) << 24);

// byte offset within a 128x128-bf16 SW128 tile (blocked atoms: 8 rows x 64 bf16)
__device__ __forceinline__ uint32_t tile_off(int row, int col) {
    uint32_t off = (uint32_t)((row >> 3) + ((col >> 6) << 4)) * 1024u
                 + (uint32_t)(row & 7) * 128u + (uint32_t)(col & 63) * 2u;
    return off ^ ((off >> 3) & 0x70);
}
#endif  // HAS_TCGEN05

// ---------------------------------------------------------------------------
// Split fp32 feats into bf16 hi/lo
// ---------------------------------------------------------------------------
__global__ __launch_bounds__(256)
void k_convert(const float* __restrict__ f) {
    int i = blockIdx.x * 256 + threadIdx.x;
    if (i < NN * DD) {
        float x = f[i];
        __nv_bfloat16 h = __float2bfloat16(x);
        g_hi[i] = h;
        g_lo[i] = __float2bfloat16(x - __bfloat162float(h));
    }
}

// ---------------------------------------------------------------------------
// tcgen05 tile kernel. PASS=0: Neg_i, sum_pos d, cnt. PASS=1: sum_pos log(e^d+Neg_i)
// grid (64, 64) tiles of 128x128. 128 threads.
// ---------------------------------------------------------------------------
template <int PASS>
__global__ __launch_bounds__(128, 1)
void k_pass(const int* __restrict__ labels) {
#if HAS_TCGEN05
    extern __shared__ char smem[];
    const uint32_t sb = smem_u32(smem);
    const int tid = threadIdx.x;
    const int wid = tid >> 5;
    const int iBase = blockIdx.x * 128;
    const int jBase = blockIdx.y * 128;
    int* labJ = (int*)(smem + OFF_LABJ);

    if (tid == 0) MBAR_INIT(sb + OFF_MBAR, 1);
    if (wid == 0) { TCG_ALLOC(sb + OFF_TMEM, 128); TCG_RELINQ(); }
    __syncthreads();
    uint32_t tmem;
    asm volatile("ld.shared.b32 %0, [%1];" : "=r"(tmem) : "r"(sb + OFF_TMEM));

    // ---- load tiles: thread t owns row t of each tile (128 bf16 = 8x uint4)
    {
        const uint4* ahi = (const uint4*)(g_hi + (size_t)(iBase + tid) * DD);
        const uint4* alo = (const uint4*)(g_lo + (size_t)(iBase + tid) * DD);
        const uint4* bhi = (const uint4*)(g_hi + (size_t)(jBase + tid) * DD);
        const uint4* blo = (const uint4*)(g_lo + (size_t)(jBase + tid) * DD);
#pragma unroll
        for (int c8 = 0; c8 < 16; c8++) {
            uint32_t o = tile_off(tid, c8 * 8);
            *(uint4*)(smem + SM_AHI + o) = ahi[c8];
            *(uint4*)(smem + SM_ALO + o) = alo[c8];
            *(uint4*)(smem + SM_BHI + o) = bhi[c8];
            *(uint4*)(smem + SM_BLO + o) = blo[c8];
        }
        labJ[tid] = labels[jBase + tid];
    }
    __syncthreads();

    // ---- MMA: hi*hi + hi*lo + lo*hi, K=128 each (8 steps of K=16)
    if (wid == 0) {
        FENCE_ASYNC_SHARED();
        uint32_t lid = tid & 31;
        if (lid == 0) {
            uint64_t aH = DESC_BASE | ((uint64_t)((sb + SM_AHI) >> 4) & 0x3FFF);
            uint64_t aL = DESC_BASE | ((uint64_t)((sb + SM_ALO) >> 4) & 0x3FFF);
            uint64_t bH = DESC_BASE | ((uint64_t)((sb + SM_BHI) >> 4) & 0x3FFF);
            uint64_t bL = DESC_BASE | ((uint64_t)((sb + SM_BLO) >> 4) & 0x3FFF);
            const uint64_t offs[8] = {0, 2, 4, 6, 1024, 1026, 1028, 1030};
            uint32_t en = 0;
#pragma unroll
            for (int s = 0; s < 8; s++) { mma_f16_ss(tmem, aH + offs[s], bH + offs[s], IDESC, en); en = 1; }
#pragma unroll
            for (int s = 0; s < 8; s++) mma_f16_ss(tmem, aH + offs[s], bL + offs[s], IDESC, 1);
#pragma unroll
            for (int s = 0; s < 8; s++) mma_f16_ss(tmem, aL + offs[s], bH + offs[s], IDESC, 1);
            TCG_COMMIT(sb + OFF_MBAR);
        }
    }
    __syncthreads();
    MBAR_WAIT(sb + OFF_MBAR, 0);
    TCG_FENCE_AFTER();

    // ---- epilogue: thread t handles global row iBase + t (lanes = tid)
    const int gRow = iBase + tid;
    const int myLab = labels[gRow];
    float negv = 0.0f;
    if (PASS == 1) negv = g_neg[gRow];

    float negA = 0.0f, posD = 0.0f, cntA = 0.0f, Tacc = 0.0f;
#pragma unroll
    for (int c0 = 0; c0 < 128; c0 += 32) {
        uint32_t r[32];
        LDTM_X32(r, tmem + c0);
        TCG_WAIT_LD();
#pragma unroll
        for (int cc = 0; cc < 32; cc++) {
            float dot = __uint_as_float(r[cc]);
            float d = 10.0f * dot - 10.0f;
            int j = jBase + c0 + cc;
            bool same = (labJ[c0 + cc] == myLab);
            if (PASS == 0) {
                if (!same) negA += __expf(d);
                else if (j != gRow) { posD += d; cntA += 1.0f; }
            } else {
                if (same && j != gRow) Tacc += __logf(__expf(d) + negv);
            }
        }
    }
    TCG_FENCE_BEFORE();

    if (PASS == 0) {
        atomicAdd(&g_neg[gRow], negA);
        atomicAdd(&g_posd[gRow], posD);
        atomicAdd(&g_cnt[gRow], cntA);
    } else {
        atomicAdd(&g_T[gRow], Tacc);
    }

    __syncthreads();
    if (tid == 0) MBAR_INVAL(sb + OFF_MBAR);
    __syncthreads();
    if (wid == 0) TCG_DEALLOC(tmem, 128);
#endif  // HAS_TCGEN05
}

// ---------------------------------------------------------------------------
// Final reduction: loss = mean_i [ -(T/Tb) * (posD_i - T_i) / cnt_i ]
// ---------------------------------------------------------------------------
__global__ __launch_bounds__(256)
void k_final(float* __restrict__ out) {
    const int tid = threadIdx.x;
    float s = 0.0f;
    for (int i = tid; i < NN; i += 256) {
        float mlp = (g_posd[i] - g_T[i]) / g_cnt[i];
        s += -(0.1f / 0.07f) * mlp;
    }
    __shared__ float sS[256];
    sS[tid] = s;
    __syncthreads();
    for (int k = 128; k > 0; k >>= 1) {
        if (tid < k) sS[tid] += sS[tid + k];
        __syncthreads();
    }
    if (tid == 0) out[0] = sS[0] / (float)NN;
}

// ---------------------------------------------------------------------------
extern "C" void kernel_launch(void* const* d_in, const int* in_sizes, int n_in,
                              void* d_out, int out_size) {
    const float* feats = (const float*)d_in[0];
    const int* labels = (const int*)d_in[1];
    float* out = (float*)d_out;

    void* p;
    cudaGetSymbolAddress(&p, g_neg);  cudaMemsetAsync(p, 0, NN * sizeof(float));
    cudaGetSymbolAddress(&p, g_posd); cudaMemsetAsync(p, 0, NN * sizeof(float));
    cudaGetSymbolAddress(&p, g_cnt);  cudaMemsetAsync(p, 0, NN * sizeof(float));
    cudaGetSymbolAddress(&p, g_T);    cudaMemsetAsync(p, 0, NN * sizeof(float));

    cudaFuncSetAttribute(k_pass<0>, cudaFuncAttributeMaxDynamicSharedMemorySize, SM_TOTAL);
    cudaFuncSetAttribute(k_pass<1>, cudaFuncAttributeMaxDynamicSharedMemorySize, SM_TOTAL);

    k_convert<<<(NN * DD + 255) / 256, 256>>>(feats);
    dim3 grid(NN / 128, NN / 128);
    k_pass<0><<<grid, 128, SM_TOTAL>>>(labels);
    k_pass<1><<<grid, 128, SM_TOTAL>>>(labels);
    k_final<<<1, 256>>>(out);
}

// round 6
// speedup vs baseline: 2.3624x; 2.3094x over previous
#include <cuda_runtime.h>
#include <cuda_bf16.h>
#include <cstdint>
#include <math.h>

#define NN 8192
#define DD 128
#define JTILES 8          // j-tiles per CTA

// tcgen05 is an arch-specific ('a') feature: only emit it on the sm_103a /
// sm_100a compilation paths. The plain compute_103 path gets empty kernel
// bodies; at runtime the exact-match sm_103a cubin is selected.
#if defined(__CUDA_ARCH__) && \
    (defined(__CUDA_ARCH_FEAT_SM103_ALL) || defined(__CUDA_ARCH_FEAT_SM100_ALL) || \
     defined(__CUDA_ARCH_SPECIFIC__) || defined(__CUDA_ARCH_FAMILY_SPECIFIC__))
#define HAS_TCGEN05 1
#else
#define HAS_TCGEN05 0
#endif

// ---------------- scratch (static device memory; no runtime alloc) ----------
__device__ __nv_bfloat16 g_hi[(size_t)NN * DD];
__device__ __nv_bfloat16 g_lo[(size_t)NN * DD];
__device__ float g_neg[NN];
__device__ float g_posd[NN];
__device__ float g_cnt[NN];
__device__ float g_s1[NN];
__device__ float g_s2[NN];
__device__ float g_s3[NN];

// ---------------- SMEM layout ----------------------------------------------
#define OFF_TMEM 0
#define OFF_MBAR0 8
#define OFF_MBAR1 16
#define OFF_LABJ 32           // int[2][128] = 1024 B
#define SM_AHI 2048
#define SM_ALO (SM_AHI + 32768)
#define SM_B0  (SM_ALO + 32768)
#define BSTRIDE 65536         // per-stage: BHI(32KB) + BLO(32KB)
#define SM_TOTAL (SM_B0 + 2 * BSTRIDE)   // 198656 B

#if HAS_TCGEN05
// ---------------- PTX helpers ----------------------------------------------
__device__ __forceinline__ uint32_t smem_u32(const void* p) {
    uint32_t a;
    asm("{ .reg .u64 t; cvta.to.shared.u64 t, %1; cvt.u32.u64 %0, t; }" : "=r"(a) : "l"(p));
    return a;
}

#define TCG_ALLOC(sm, n) asm volatile("tcgen05.alloc.cta_group::1.sync.aligned.shared::cta.b32 [%0], %1;" :: "r"(sm), "r"(n) : "memory")
#define TCG_DEALLOC(t, n) asm volatile("tcgen05.dealloc.cta_group::1.sync.aligned.b32 %0, %1;" :: "r"(t), "r"(n))
#define TCG_RELINQ() asm volatile("tcgen05.relinquish_alloc_permit.cta_group::1.sync.aligned;")
#define TCG_COMMIT(mb) asm volatile("tcgen05.commit.cta_group::1.mbarrier::arrive::one.shared::cluster.b64 [%0];" :: "r"(mb) : "memory")
#define TCG_WAIT_LD() asm volatile("tcgen05.wait::ld.sync.aligned;" ::: "memory")
#define TCG_FENCE_BEFORE() asm volatile("tcgen05.fence::before_thread_sync;" ::: "memory")
#define TCG_FENCE_AFTER() asm volatile("tcgen05.fence::after_thread_sync;" ::: "memory")
#define FENCE_ASYNC_SHARED() asm volatile("fence.proxy.async.shared::cta;" ::: "memory")
#define MBAR_INIT(mb, c) asm volatile("mbarrier.init.shared.b64 [%0], %1;" :: "r"(mb), "r"(c) : "memory")
#define MBAR_INVAL(mb) asm volatile("mbarrier.inval.shared.b64 [%0];" :: "r"(mb) : "memory")

#define MBAR_WAIT(mb, ph) do { \
    uint32_t _m = (mb); uint32_t _p = (ph); uint32_t _d; \
    asm volatile("{ .reg .pred p; mbarrier.try_wait.parity.acquire.cta.shared::cta.b64 p, [%1], %2; selp.b32 %0,1,0,p; }" \
                 : "=r"(_d) : "r"(_m), "r"(_p) : "memory"); \
    if (!_d) { \
        asm volatile("{ .reg .pred P1; WL_%=: mbarrier.try_wait.parity.acquire.cta.shared::cta.b64 P1, [%0], %1, 0x989680; @P1 bra.uni WD_%=; bra.uni WL_%=; WD_%=: }" \
                     :: "r"(_m), "r"(_p) : "memory"); \
    } } while (0)

#define LDTM_X32(r, addr) \
    asm volatile("tcgen05.ld.sync.aligned.32x32b.x32.b32 " \
        "{%0,%1,%2,%3,%4,%5,%6,%7,%8,%9,%10,%11,%12,%13,%14,%15," \
        "%16,%17,%18,%19,%20,%21,%22,%23,%24,%25,%26,%27,%28,%29,%30,%31}, [%32];" \
        : "=r"((r)[0]),"=r"((r)[1]),"=r"((r)[2]),"=r"((r)[3]),"=r"((r)[4]),"=r"((r)[5]),"=r"((r)[6]),"=r"((r)[7]), \
          "=r"((r)[8]),"=r"((r)[9]),"=r"((r)[10]),"=r"((r)[11]),"=r"((r)[12]),"=r"((r)[13]),"=r"((r)[14]),"=r"((r)[15]), \
          "=r"((r)[16]),"=r"((r)[17]),"=r"((r)[18]),"=r"((r)[19]),"=r"((r)[20]),"=r"((r)[21]),"=r"((r)[22]),"=r"((r)[23]), \
          "=r"((r)[24]),"=r"((r)[25]),"=r"((r)[26]),"=r"((r)[27]),"=r"((r)[28]),"=r"((r)[29]),"=r"((r)[30]),"=r"((r)[31]) \
        : "r"(addr))

__device__ __forceinline__ void mma_f16_ss(uint32_t d, uint64_t a, uint64_t b,
                                           uint32_t idesc, uint32_t en) {
    asm volatile(
        "{\n\t.reg .pred p;\n\t"
        "setp.ne.u32 p, %5, 0;\n\t"
        "tcgen05.mma.cta_group::1.kind::f16 [%0], %1, %2, %3, {%4,%4,%4,%4}, p;\n\t}"
        :: "r"(d), "l"(a), "l"(b), "r"(idesc), "r"(0u), "r"(en) : "memory");
}

// SW128 K-major descriptor base: layout=SW128, version=1, SBO=64, LBO=1
static constexpr uint64_t DESC_BASE =
    (uint64_t(2) << 61) | (uint64_t(1) << 46) | (uint64_t(64) << 32) | (uint64_t(1) << 16);

// idesc: D=F32, A=BF16, B=BF16, N=128, M=128 (K-major both)
static constexpr uint32_t IDESC =
    (1u << 4) | (1u << 7) | (1u << 10) | ((128u / 8) << 17) | ((128u / 16) << 24);

// byte offset within a 128x128-bf16 SW128 tile (blocked atoms: 8 rows x 64 bf16)
__device__ __forceinline__ uint32_t tile_off(int row, int col) {
    uint32_t off = (uint32_t)((row >> 3) + ((col >> 6) << 4)) * 1024u
                 + (uint32_t)(row & 7) * 128u + (uint32_t)(col & 63) * 2u;
    return off ^ ((off >> 3) & 0x70);
}
#endif  // HAS_TCGEN05

// ---------------------------------------------------------------------------
// Split fp32 feats into bf16 hi/lo
// ---------------------------------------------------------------------------
__global__ __launch_bounds__(256)
void k_convert(const float* __restrict__ f) {
    int i = blockIdx.x * 256 + threadIdx.x;
    if (i < NN * DD) {
        float x = f[i];
        __nv_bfloat16 h = __float2bfloat16(x);
        g_hi[i] = h;
        g_lo[i] = __float2bfloat16(x - __bfloat162float(h));
    }
}

// ---------------------------------------------------------------------------
// Persistent-i-tile pipelined kernel. Grid (64, 8): CTA (bi, bj) owns i-tile
// bi and processes j-tiles bj*8 .. bj*8+7 with double-buffered B and
// ping-pong TMEM accumulators. Single pass: accumulates per row i
//   Neg, sum_pos d, cnt, S1 = sum_pos e^d, S2 = sum_pos e^2d, S3 = sum_pos e^3d
// ---------------------------------------------------------------------------
__global__ __launch_bounds__(128, 1)
void k_tiles(const int* __restrict__ labels) {
#if HAS_TCGEN05
    extern __shared__ char smem[];
    const uint32_t sb = smem_u32(smem);
    const int tid = threadIdx.x;
    const int iBase = blockIdx.x * 128;
    const int jGrp = blockIdx.y;
    int* labJ = (int*)(smem + OFF_LABJ);    // [2][128]

    if (tid == 0) { MBAR_INIT(sb + OFF_MBAR0, 1); MBAR_INIT(sb + OFF_MBAR1, 1); }
    if (tid < 32) { TCG_ALLOC(sb + OFF_TMEM, 256); TCG_RELINQ(); }
    __syncthreads();
    uint32_t tmem;
    asm volatile("ld.shared.b32 %0, [%1];" : "=r"(tmem) : "r"(sb + OFF_TMEM));

    // ---- load A tile (hi+lo), resident for all 8 j-tiles
    {
        const uint4* ahi = (const uint4*)(g_hi + (size_t)(iBase + tid) * DD);
        const uint4* alo = (const uint4*)(g_lo + (size_t)(iBase + tid) * DD);
#pragma unroll
        for (int c8 = 0; c8 < 16; c8++) {
            uint32_t o = tile_off(tid, c8 * 8);
            *(uint4*)(smem + SM_AHI + o) = ahi[c8];
            *(uint4*)(smem + SM_ALO + o) = alo[c8];
        }
    }

    const uint64_t aH = DESC_BASE | ((uint64_t)((sb + SM_AHI) >> 4) & 0x3FFF);
    const uint64_t aL = DESC_BASE | ((uint64_t)((sb + SM_ALO) >> 4) & 0x3FFF);

    // ---- stage loader: B tile s into buffer s&1
#define LOADB(s) do { \
        int _jb = (jGrp * JTILES + (s)) * 128; \
        const uint4* _bhi = (const uint4*)(g_hi + (size_t)(_jb + tid) * DD); \
        const uint4* _blo = (const uint4*)(g_lo + (size_t)(_jb + tid) * DD); \
        char* _BH = smem + SM_B0 + ((s) & 1) * BSTRIDE; \
        _Pragma("unroll") \
        for (int _c8 = 0; _c8 < 16; _c8++) { \
            uint32_t _o = tile_off(tid, _c8 * 8); \
            *(uint4*)(_BH + _o) = _bhi[_c8]; \
            *(uint4*)(_BH + 32768 + _o) = _blo[_c8]; \
        } \
        labJ[((s) & 1) * 128 + tid] = labels[_jb + tid]; \
    } while (0)

    // ---- MMA issuer for stage s (tid 0 only): 24 K16 dispatches, en=0 first
#define ISSUE(s) do { \
        uint32_t _dtm = tmem + ((s) & 1) * 128; \
        uint32_t _bb = sb + SM_B0 + ((s) & 1) * BSTRIDE; \
        uint64_t _bH = DESC_BASE | ((uint64_t)(_bb >> 4) & 0x3FFF); \
        uint64_t _bL = DESC_BASE | ((uint64_t)((_bb + 32768) >> 4) & 0x3FFF); \
        const uint64_t _offs[8] = {0, 2, 4, 6, 1024, 1026, 1028, 1030}; \
        uint32_t _en = 0; \
        _Pragma("unroll") \
        for (int _k = 0; _k < 8; _k++) { mma_f16_ss(_dtm, aH + _offs[_k], _bH + _offs[_k], IDESC, _en); _en = 1; } \
        _Pragma("unroll") \
        for (int _k = 0; _k < 8; _k++) mma_f16_ss(_dtm, aH + _offs[_k], _bL + _offs[_k], IDESC, 1); \
        _Pragma("unroll") \
        for (int _k = 0; _k < 8; _k++) mma_f16_ss(_dtm, aL + _offs[_k], _bH + _offs[_k], IDESC, 1); \
        TCG_COMMIT(sb + OFF_MBAR0 + ((s) & 1) * 8); \
    } while (0)

    LOADB(0);
    __syncthreads();
    if (tid == 0) { FENCE_ASYNC_SHARED(); ISSUE(0); }

    const int gRow = iBase + tid;
    const int myLab = labels[gRow];
    float negA = 0.0f, posD = 0.0f, cntA = 0.0f, S1 = 0.0f, S2 = 0.0f, S3 = 0.0f;

    for (int s = 0; s < JTILES; s++) {
        const int nb = s + 1;
        if (nb < JTILES) LOADB(nb);
        __syncthreads();
        if (nb < JTILES && tid == 0) { FENCE_ASYNC_SHARED(); ISSUE(nb); }

        MBAR_WAIT(sb + OFF_MBAR0 + (s & 1) * 8, (s >> 1) & 1);
        TCG_FENCE_AFTER();

        const int jb = (jGrp * JTILES + s) * 128;
        const uint32_t dtm = tmem + (s & 1) * 128;
        const int* lj = labJ + (s & 1) * 128;
#pragma unroll
        for (int c0 = 0; c0 < 128; c0 += 32) {
            uint32_t r[32];
            LDTM_X32(r, dtm + c0);
            TCG_WAIT_LD();
#pragma unroll
            for (int cc = 0; cc < 32; cc++) {
                float dot = __uint_as_float(r[cc]);
                float d = 10.0f * dot - 10.0f;
                float e = __expf(d);
                int j = jb + c0 + cc;
                bool same = (lj[c0 + cc] == myLab);
                if (!same) {
                    negA += e;
                } else if (j != gRow) {
                    posD += d; cntA += 1.0f;
                    S1 += e; S2 += e * e; S3 += e * e * e;
                }
            }
        }
        TCG_FENCE_BEFORE();
        __syncthreads();   // protect buffers (B/labJ) before next-iter load
    }

    atomicAdd(&g_neg[gRow], negA);
    atomicAdd(&g_posd[gRow], posD);
    atomicAdd(&g_cnt[gRow], cntA);
    atomicAdd(&g_s1[gRow], S1);
    atomicAdd(&g_s2[gRow], S2);
    atomicAdd(&g_s3[gRow], S3);

    __syncthreads();
    if (tid == 0) { MBAR_INVAL(sb + OFF_MBAR0); MBAR_INVAL(sb + OFF_MBAR1); }
    __syncthreads();
    if (tid < 32) TCG_DEALLOC(tmem, 256);
#undef LOADB
#undef ISSUE
#endif  // HAS_TCGEN05
}

// ---------------------------------------------------------------------------
// Final: sum_pos log(e^d + Neg) = cnt*ln(Neg) + S1/Neg - S2/(2 Neg^2) + S3/(3 Neg^3)
// loss = mean_i [ -(T/Tb) * (posD_i - that) / cnt_i ]
// ---------------------------------------------------------------------------
__global__ __launch_bounds__(1024)
void k_final(float* __restrict__ out) {
    const int tid = threadIdx.x;
    float s = 0.0f;
    for (int i = tid; i < NN; i += 1024) {
        float neg = g_neg[i];
        float inv = 1.0f / neg;
        float lsum = g_cnt[i] * __logf(neg)
                   + g_s1[i] * inv
                   - 0.5f * g_s2[i] * inv * inv
                   + (1.0f / 3.0f) * g_s3[i] * inv * inv * inv;
        s += (g_posd[i] - lsum) / g_cnt[i];
    }
    __shared__ float sS[1024];
    sS[tid] = s;
    __syncthreads();
    for (int k = 512; k > 0; k >>= 1) {
        if (tid < k) sS[tid] += sS[tid + k];
        __syncthreads();
    }
    if (tid == 0) out[0] = -(0.1f / 0.07f) * sS[0] / (float)NN;
}

// ---------------------------------------------------------------------------
extern "C" void kernel_launch(void* const* d_in, const int* in_sizes, int n_in,
                              void* d_out, int out_size) {
    const float* feats = (const float*)d_in[0];
    const int* labels = (const int*)d_in[1];
    float* out = (float*)d_out;

    void* p;
    cudaGetSymbolAddress(&p, g_neg);  cudaMemsetAsync(p, 0, NN * sizeof(float));
    cudaGetSymbolAddress(&p, g_posd); cudaMemsetAsync(p, 0, NN * sizeof(float));
    cudaGetSymbolAddress(&p, g_cnt);  cudaMemsetAsync(p, 0, NN * sizeof(float));
    cudaGetSymbolAddress(&p, g_s1);   cudaMemsetAsync(p, 0, NN * sizeof(float));
    cudaGetSymbolAddress(&p, g_s2);   cudaMemsetAsync(p, 0, NN * sizeof(float));
    cudaGetSymbolAddress(&p, g_s3);   cudaMemsetAsync(p, 0, NN * sizeof(float));

    cudaFuncSetAttribute(k_tiles, cudaFuncAttributeMaxDynamicSharedMemorySize, SM_TOTAL);

    k_convert<<<(NN * DD + 255) / 256, 256>>>(feats);
    dim3 grid(NN / 128, JTILES);   // (64, 8)
    k_tiles<<<grid, 128, SM_TOTAL>>>(labels);
    k_final<<<1, 1024>>>(out);
}

// round 9
// speedup vs baseline: 4.5403x; 1.9219x over previous
#include <cuda_runtime.h>
#include <cuda_bf16.h>
#include <cstdint>
#include <math.h>

#define NN 8192
#define DD 128
#define JTILES 8          // j-tiles per CTA

#if defined(__CUDA_ARCH__) && \
    (defined(__CUDA_ARCH_FEAT_SM103_ALL) || defined(__CUDA_ARCH_FEAT_SM100_ALL) || \
     defined(__CUDA_ARCH_SPECIFIC__) || defined(__CUDA_ARCH_FAMILY_SPECIFIC__))
#define HAS_TCGEN05 1
#else
#define HAS_TCGEN05 0
#endif

// ---------------- scratch (static device memory; no runtime alloc) ----------
__device__ __nv_bfloat16 g_hi[(size_t)NN * DD];
__device__ __nv_bfloat16 g_lo[(size_t)NN * DD];
__device__ float g_neg[NN];
__device__ float g_dotp[NN];
__device__ float g_cnt[NN];
__device__ float g_s1[NN];
__device__ float g_s2[NN];
__device__ float g_s3[NN];

// ---------------- SMEM layout (all tile bases 1024-aligned) ----------------
#define OFF_TMEM 0
#define OFF_MBAR0 8
#define OFF_MBAR1 16
#define OFF_LAB8 1024          // int[1024] = 4 KB (labels for all 8 j-tiles)
#define SM_AHI 5120
#define SM_ALO (SM_AHI + 32768)        // 37888
#define SM_B0  (SM_ALO + 32768)        // 70656
#define BSTRIDE 65536                  // per stage: BHI(32K) + BLO(32K)
#define SM_TOTAL (SM_B0 + 2 * BSTRIDE) // 201728 B

#if HAS_TCGEN05
// ---------------- PTX helpers ----------------------------------------------
__device__ __forceinline__ uint32_t smem_u32(const void* p) {
    uint32_t a;
    asm("{ .reg .u64 t; cvta.to.shared.u64 t, %1; cvt.u32.u64 %0, t; }" : "=r"(a) : "l"(p));
    return a;
}

#define TCG_ALLOC(sm, n) asm volatile("tcgen05.alloc.cta_group::1.sync.aligned.shared::cta.b32 [%0], %1;" :: "r"(sm), "r"(n) : "memory")
#define TCG_DEALLOC(t, n) asm volatile("tcgen05.dealloc.cta_group::1.sync.aligned.b32 %0, %1;" :: "r"(t), "r"(n))
#define TCG_RELINQ() asm volatile("tcgen05.relinquish_alloc_permit.cta_group::1.sync.aligned;")
#define TCG_COMMIT(mb) asm volatile("tcgen05.commit.cta_group::1.mbarrier::arrive::one.shared::cluster.b64 [%0];" :: "r"(mb) : "memory")
#define TCG_WAIT_LD() asm volatile("tcgen05.wait::ld.sync.aligned;" ::: "memory")
#define TCG_FENCE_BEFORE() asm volatile("tcgen05.fence::before_thread_sync;" ::: "memory")
#define TCG_FENCE_AFTER() asm volatile("tcgen05.fence::after_thread_sync;" ::: "memory")
#define FENCE_ASYNC_SHARED() asm volatile("fence.proxy.async.shared::cta;" ::: "memory")
#define MBAR_INIT(mb, c) asm volatile("mbarrier.init.shared.b64 [%0], %1;" :: "r"(mb), "r"(c) : "memory")
#define MBAR_INVAL(mb) asm volatile("mbarrier.inval.shared.b64 [%0];" :: "r"(mb) : "memory")
#define CP_ASYNC16(dst, src) asm volatile("cp.async.cg.shared.global [%0], [%1], 16;" :: "r"(dst), "l"(src) : "memory")
#define CP_COMMIT() asm volatile("cp.async.commit_group;" ::: "memory")
#define CP_WAIT(n) asm volatile("cp.async.wait_group %0;" :: "n"(n) : "memory")

#define MBAR_WAIT(mb, ph) do { \
    uint32_t _m = (mb); uint32_t _p = (ph); uint32_t _d; \
    asm volatile("{ .reg .pred p; mbarrier.try_wait.parity.acquire.cta.shared::cta.b64 p, [%1], %2; selp.b32 %0,1,0,p; }" \
                 : "=r"(_d) : "r"(_m), "r"(_p) : "memory"); \
    if (!_d) { \
        asm volatile("{ .reg .pred P1; WL_%=: mbarrier.try_wait.parity.acquire.cta.shared::cta.b64 P1, [%0], %1, 0x989680; @P1 bra.uni WD_%=; bra.uni WL_%=; WD_%=: }" \
                     :: "r"(_m), "r"(_p) : "memory"); \
    } } while (0)

#define LDTM_X32(r, addr) \
    asm volatile("tcgen05.ld.sync.aligned.32x32b.x32.b32 " \
        "{%0,%1,%2,%3,%4,%5,%6,%7,%8,%9,%10,%11,%12,%13,%14,%15," \
        "%16,%17,%18,%19,%20,%21,%22,%23,%24,%25,%26,%27,%28,%29,%30,%31}, [%32];" \
        : "=r"((r)[0]),"=r"((r)[1]),"=r"((r)[2]),"=r"((r)[3]),"=r"((r)[4]),"=r"((r)[5]),"=r"((r)[6]),"=r"((r)[7]), \
          "=r"((r)[8]),"=r"((r)[9]),"=r"((r)[10]),"=r"((r)[11]),"=r"((r)[12]),"=r"((r)[13]),"=r"((r)[14]),"=r"((r)[15]), \
          "=r"((r)[16]),"=r"((r)[17]),"=r"((r)[18]),"=r"((r)[19]),"=r"((r)[20]),"=r"((r)[21]),"=r"((r)[22]),"=r"((r)[23]), \
          "=r"((r)[24]),"=r"((r)[25]),"=r"((r)[26]),"=r"((r)[27]),"=r"((r)[28]),"=r"((r)[29]),"=r"((r)[30]),"=r"((r)[31]) \
        : "r"(addr))

__device__ __forceinline__ void mma_f16_ss(uint32_t d, uint64_t a, uint64_t b,
                                           uint32_t idesc, uint32_t en) {
    asm volatile(
        "{\n\t.reg .pred p;\n\t"
        "setp.ne.u32 p, %5, 0;\n\t"
        "tcgen05.mma.cta_group::1.kind::f16 [%0], %1, %2, %3, {%4,%4,%4,%4}, p;\n\t}"
        :: "r"(d), "l"(a), "l"(b), "r"(idesc), "r"(0u), "r"(en) : "memory");
}

static constexpr uint64_t DESC_BASE =
    (uint64_t(2) << 61) | (uint64_t(1) << 46) | (uint64_t(64) << 32) | (uint64_t(1) << 16);
static constexpr uint32_t IDESC =
    (1u << 4) | (1u << 7) | (1u << 10) | ((128u / 8) << 17) | ((128u / 16) << 24);

__device__ __forceinline__ uint32_t tile_off(int row, int col) {
    uint32_t off = (uint32_t)((row >> 3) + ((col >> 6) << 4)) * 1024u
                 + (uint32_t)(row & 7) * 128u + (uint32_t)(col & 63) * 2u;
    return off ^ ((off >> 3) & 0x70);
}

__device__ __forceinline__ float fast_ex2(float x) {
    float r;
    asm("ex2.approx.f32 %0, %1;" : "=f"(r) : "f"(x));
    return r;
}
#endif  // HAS_TCGEN05

// ---------------------------------------------------------------------------
// Split fp32 feats into bf16 hi/lo (vectorized: 4 elems/thread)
// ---------------------------------------------------------------------------
__global__ __launch_bounds__(256)
void k_convert(const float* __restrict__ f) {
    int idx = blockIdx.x * 256 + threadIdx.x;   // handles 4 elements
    if (idx < NN * DD / 4) {
        float4 v = ((const float4*)f)[idx];
        __nv_bfloat16 h0 = __float2bfloat16(v.x), h1 = __float2bfloat16(v.y);
        __nv_bfloat16 h2 = __float2bfloat16(v.z), h3 = __float2bfloat16(v.w);
        __nv_bfloat162* hp = (__nv_bfloat162*)(g_hi + (size_t)idx * 4);
        __nv_bfloat162* lp = (__nv_bfloat162*)(g_lo + (size_t)idx * 4);
        hp[0] = __nv_bfloat162(h0, h1);
        hp[1] = __nv_bfloat162(h2, h3);
        lp[0] = __nv_bfloat162(__float2bfloat16(v.x - __bfloat162float(h0)),
                               __float2bfloat16(v.y - __bfloat162float(h1)));
        lp[1] = __nv_bfloat162(__float2bfloat16(v.z - __bfloat162float(h2)),
                               __float2bfloat16(v.w - __bfloat162float(h3)));
    }
}

// ---------------------------------------------------------------------------
// Persistent-i-tile pipelined kernel, 256 threads, cp.async 2-ahead B loads,
// ping-pong TMEM, branchless epilogue. Grid (64, 8).
// Accumulates per row: Neg, sum_pos dot, cnt, S1=sum_pos e, S2=sum e^2, S3=sum e^3
// ---------------------------------------------------------------------------
__global__ __launch_bounds__(256, 1)
void k_tiles(const int* __restrict__ labels) {
#if HAS_TCGEN05
    extern __shared__ char smem[];
    const uint32_t sb = smem_u32(smem);
    const int tid = threadIdx.x;
    const int iBase = blockIdx.x * 128;
    const int jGrp = blockIdx.y;
    int* lab8 = (int*)(smem + OFF_LAB8);

    if (tid == 0) { MBAR_INIT(sb + OFF_MBAR0, 1); MBAR_INIT(sb + OFF_MBAR1, 1); }
    if (tid < 32) { TCG_ALLOC(sb + OFF_TMEM, 256); TCG_RELINQ(); }
    __syncthreads();
    uint32_t tmem;
    asm volatile("ld.shared.b32 %0, [%1];" : "=r"(tmem) : "r"(sb + OFF_TMEM));

    const int lrow = tid >> 1;          // loader row 0..127
    const int lhalf = tid & 1;          // loader half 0/1

    // ---- A tile (resident): 256 threads, 8 chunks each for hi and lo
    {
        const uint4* ahi = (const uint4*)(g_hi + (size_t)(iBase + lrow) * DD + lhalf * 64);
        const uint4* alo = (const uint4*)(g_lo + (size_t)(iBase + lrow) * DD + lhalf * 64);
#pragma unroll
        for (int c = 0; c < 8; c++) {
            uint32_t o = tile_off(lrow, lhalf * 64 + c * 8);
            *(uint4*)(smem + SM_AHI + o) = ahi[c];
            *(uint4*)(smem + SM_ALO + o) = alo[c];
        }
    }
    // ---- labels for all 8 j-tiles (1024 ints)
    ((int4*)lab8)[tid] = ((const int4*)(labels + jGrp * 1024))[tid];

    const uint64_t aH = DESC_BASE | ((uint64_t)((sb + SM_AHI) >> 4) & 0x3FFF);
    const uint64_t aL = DESC_BASE | ((uint64_t)((sb + SM_ALO) >> 4) & 0x3FFF);

#define CPLOADB(s) do { \
        int _jb = (jGrp * JTILES + (s)) * 128; \
        const char* _sh = (const char*)(g_hi + (size_t)(_jb + lrow) * DD + lhalf * 64); \
        const char* _sl = (const char*)(g_lo + (size_t)(_jb + lrow) * DD + lhalf * 64); \
        uint32_t _bb = sb + SM_B0 + ((s) & 1) * BSTRIDE; \
        _Pragma("unroll") \
        for (int _c = 0; _c < 8; _c++) { \
            uint32_t _o = tile_off(lrow, lhalf * 64 + _c * 8); \
            CP_ASYNC16(_bb + _o, _sh + _c * 16); \
            CP_ASYNC16(_bb + 32768 + _o, _sl + _c * 16); \
        } \
        CP_COMMIT(); \
    } while (0)

#define ISSUE(s) do { \
        uint32_t _dtm = tmem + ((s) & 1) * 128; \
        uint32_t _bb = sb + SM_B0 + ((s) & 1) * BSTRIDE; \
        uint64_t _bH = DESC_BASE | ((uint64_t)(_bb >> 4) & 0x3FFF); \
        uint64_t _bL = DESC_BASE | ((uint64_t)((_bb + 32768) >> 4) & 0x3FFF); \
        const uint64_t _offs[8] = {0, 2, 4, 6, 1024, 1026, 1028, 1030}; \
        uint32_t _en = 0; \
        _Pragma("unroll") \
        for (int _k = 0; _k < 8; _k++) { mma_f16_ss(_dtm, aH + _offs[_k], _bH + _offs[_k], IDESC, _en); _en = 1; } \
        _Pragma("unroll") \
        for (int _k = 0; _k < 8; _k++) mma_f16_ss(_dtm, aH + _offs[_k], _bL + _offs[_k], IDESC, 1); \
        _Pragma("unroll") \
        for (int _k = 0; _k < 8; _k++) mma_f16_ss(_dtm, aL + _offs[_k], _bH + _offs[_k], IDESC, 1); \
        TCG_COMMIT(sb + OFF_MBAR0 + ((s) & 1) * 8); \
    } while (0)

    CPLOADB(0);
    CPLOADB(1);
    CP_WAIT(1);              // B(0) resident
    __syncthreads();         // A, labels, B(0) visible block-wide
    if (tid == 0) { FENCE_ASYNC_SHARED(); ISSUE(0); }

    // ---- epilogue mapping: row = (wid&3)*32 + lane, col half = wid>>2
    const int lane = tid & 31;
    const int row = ((tid >> 5) & 3) * 32 + lane;
    const int colBase = (tid >> 7) * 64;
    const int gRow = iBase + row;
    const int myLab = labels[gRow];
    const float C1 = 14.4269504089f;    // 10 * log2(e)

    float negA = 0.0f, dotP = 0.0f, cntA = 0.0f, S1 = 0.0f, S2 = 0.0f, S3 = 0.0f;

    for (int s = 0; s < JTILES; s++) {
        MBAR_WAIT(sb + OFF_MBAR0 + (s & 1) * 8, (s >> 1) & 1);
        TCG_FENCE_AFTER();

        if (s + 2 < JTILES) CPLOADB(s + 2);           // into buf (s&1), now free
        if (s + 1 < JTILES) {
            if (s + 2 < JTILES) CP_WAIT(1); else CP_WAIT(0);  // B(s+1) resident
            __syncthreads();
            if (tid == 0) { FENCE_ASYNC_SHARED(); ISSUE(s + 1); }
        }

        const int jb = (jGrp * JTILES + s) * 128;
        const uint32_t dtm = tmem + (s & 1) * 128 + colBase;
        const int* lj = lab8 + s * 128 + colBase;

        uint32_t r0[32], r1[32];
        LDTM_X32(r0, dtm);
        LDTM_X32(r1, dtm + 32);
        TCG_WAIT_LD();

#pragma unroll
        for (int half = 0; half < 2; half++) {
            const uint32_t* rr = half ? r1 : r0;
#pragma unroll
            for (int cc = 0; cc < 32; cc++) {
                float dot = __uint_as_float(rr[cc]);
                float e = fast_ex2(fmaf(dot, C1, -C1));   // exp(10*dot - 10)
                int col = colBase + half * 32 + cc;
                int j = jb + col;
                bool same = (lj[half * 32 + cc] == myLab);
                float wP = (same && (j != gRow)) ? 1.0f : 0.0f;
                float wN = same ? 0.0f : 1.0f;
                negA = fmaf(wN, e, negA);
                dotP = fmaf(wP, dot, dotP);
                cntA += wP;
                S1 = fmaf(wP, e, S1);
                float ew = wP * e;
                float e2 = e * e;
                S2 = fmaf(ew, e, S2);
                S3 = fmaf(ew, e2, S3);
            }
        }
        TCG_FENCE_BEFORE();
    }

    atomicAdd(&g_neg[gRow], negA);
    atomicAdd(&g_dotp[gRow], dotP);
    atomicAdd(&g_cnt[gRow], cntA);
    atomicAdd(&g_s1[gRow], S1);
    atomicAdd(&g_s2[gRow], S2);
    atomicAdd(&g_s3[gRow], S3);

    __syncthreads();
    if (tid == 0) { MBAR_INVAL(sb + OFF_MBAR0); MBAR_INVAL(sb + OFF_MBAR1); }
    __syncthreads();
    if (tid < 32) TCG_DEALLOC(tmem, 256);
#undef CPLOADB
#undef ISSUE
#endif  // HAS_TCGEN05
}

// ---------------------------------------------------------------------------
// Final: posD = 10*dotP - 10*cnt;
// sum_pos log(e^d+Neg) = cnt*ln(Neg) + S1/Neg - S2/(2 Neg^2) + S3/(3 Neg^3)
// loss = mean_i [ -(T/Tb) * (posD - that) / cnt ]
// ---------------------------------------------------------------------------
__global__ __launch_bounds__(1024)
void k_final(float* __restrict__ out) {
    const int tid = threadIdx.x;
    float s = 0.0f;
#pragma unroll
    for (int it = 0; it < NN / 1024; it++) {
        int i = it * 1024 + tid;
        float neg = g_neg[i];
        float cnt = g_cnt[i];
        float inv = 1.0f / neg;
        float posD = 10.0f * g_dotp[i] - 10.0f * cnt;
        float lsum = cnt * __logf(neg)
                   + g_s1[i] * inv
                   - 0.5f * g_s2[i] * inv * inv
                   + (1.0f / 3.0f) * g_s3[i] * inv * inv * inv;
        s += (posD - lsum) / cnt;
    }
    __shared__ float sS[1024];
    sS[tid] = s;
    __syncthreads();
    for (int k = 512; k > 0; k >>= 1) {
        if (tid < k) sS[tid] += sS[tid + k];
        __syncthreads();
    }
    if (tid == 0) out[0] = -(0.1f / 0.07f) * sS[0] / (float)NN;
}

// ---------------------------------------------------------------------------
extern "C" void kernel_launch(void* const* d_in, const int* in_sizes, int n_in,
                              void* d_out, int out_size) {
    const float* feats = (const float*)d_in[0];
    const int* labels = (const int*)d_in[1];
    float* out = (float*)d_out;

    void* p;
    cudaGetSymbolAddress(&p, g_neg);  cudaMemsetAsync(p, 0, NN * sizeof(float));
    cudaGetSymbolAddress(&p, g_dotp); cudaMemsetAsync(p, 0, NN * sizeof(float));
    cudaGetSymbolAddress(&p, g_cnt);  cudaMemsetAsync(p, 0, NN * sizeof(float));
    cudaGetSymbolAddress(&p, g_s1);   cudaMemsetAsync(p, 0, NN * sizeof(float));
    cudaGetSymbolAddress(&p, g_s2);   cudaMemsetAsync(p, 0, NN * sizeof(float));
    cudaGetSymbolAddress(&p, g_s3);   cudaMemsetAsync(p, 0, NN * sizeof(float));

    cudaFuncSetAttribute(k_tiles, cudaFuncAttributeMaxDynamicSharedMemorySize, SM_TOTAL);

    k_convert<<<(NN * DD / 4 + 255) / 256, 256>>>(feats);
    dim3 grid(NN / 128, JTILES);   // (64, 8)
    k_tiles<<<grid, 256, SM_TOTAL>>>(labels);
    k_final<<<1, 1024>>>(out);
}

// round 10
// speedup vs baseline: 4.9678x; 1.0942x over previous
#include <cuda_runtime.h>
#include <cuda_bf16.h>
#include <cstdint>
#include <math.h>

#define NN 8192
#define DD 128
#define NTILE 64           // NN/128
#define TTOT (NTILE * NTILE)
#define NCTA 148

#if defined(__CUDA_ARCH__) && \
    (defined(__CUDA_ARCH_FEAT_SM103_ALL) || defined(__CUDA_ARCH_FEAT_SM100_ALL) || \
     defined(__CUDA_ARCH_SPECIFIC__) || defined(__CUDA_ARCH_FAMILY_SPECIFIC__))
#define HAS_TCGEN05 1
#else
#define HAS_TCGEN05 0
#endif

// ---------------- scratch (static device memory; no runtime alloc) ----------
__device__ __nv_bfloat16 g_hi[(size_t)NN * DD];
__device__ __nv_bfloat16 g_lo[(size_t)NN * DD];
__device__ float g_Te[NN], g_Te1[NN], g_Td[NN], g_Td1[NN], g_Te2[NN], g_Te21[NN];
__device__ float g_de[NN], g_dd[NN];

// ---------------- SMEM layout (tile bases 1024-aligned) ---------------------
#define OFF_TMEM 0
#define OFF_MBAR0 8
#define OFF_LABF 1024          // float[4][128] = 2 KB
#define SM_AHI 4096
#define SM_ALO (SM_AHI + 32768)
#define SM_B0  (SM_ALO + 32768)
#define BSTRIDE 65536
#define SM_TOTAL (SM_B0 + 2 * BSTRIDE)   // 200704 B

#if HAS_TCGEN05
// ---------------- PTX helpers ----------------------------------------------
__device__ __forceinline__ uint32_t smem_u32(const void* p) {
    uint32_t a;
    asm("{ .reg .u64 t; cvta.to.shared.u64 t, %1; cvt.u32.u64 %0, t; }" : "=r"(a) : "l"(p));
    return a;
}
#define TCG_ALLOC(sm, n) asm volatile("tcgen05.alloc.cta_group::1.sync.aligned.shared::cta.b32 [%0], %1;" :: "r"(sm), "r"(n) : "memory")
#define TCG_DEALLOC(t, n) asm volatile("tcgen05.dealloc.cta_group::1.sync.aligned.b32 %0, %1;" :: "r"(t), "r"(n))
#define TCG_RELINQ() asm volatile("tcgen05.relinquish_alloc_permit.cta_group::1.sync.aligned;")
#define TCG_COMMIT(mb) asm volatile("tcgen05.commit.cta_group::1.mbarrier::arrive::one.shared::cluster.b64 [%0];" :: "r"(mb) : "memory")
#define TCG_WAIT_LD() asm volatile("tcgen05.wait::ld.sync.aligned;" ::: "memory")
#define TCG_FENCE_BEFORE() asm volatile("tcgen05.fence::before_thread_sync;" ::: "memory")
#define TCG_FENCE_AFTER() asm volatile("tcgen05.fence::after_thread_sync;" ::: "memory")
#define FENCE_ASYNC_SHARED() asm volatile("fence.proxy.async.shared::cta;" ::: "memory")
#define MBAR_INIT(mb, c) asm volatile("mbarrier.init.shared.b64 [%0], %1;" :: "r"(mb), "r"(c) : "memory")
#define MBAR_INVAL(mb) asm volatile("mbarrier.inval.shared.b64 [%0];" :: "r"(mb) : "memory")
#define CP_ASYNC16(dst, src) asm volatile("cp.async.cg.shared.global [%0], [%1], 16;" :: "r"(dst), "l"(src) : "memory")
#define CP_COMMIT() asm volatile("cp.async.commit_group;" ::: "memory")
#define CP_WAIT(n) asm volatile("cp.async.wait_group %0;" :: "n"(n) : "memory")

#define MBAR_WAIT(mb, ph) do { \
    uint32_t _m = (mb); uint32_t _p = (ph); uint32_t _d; \
    asm volatile("{ .reg .pred p; mbarrier.try_wait.parity.acquire.cta.shared::cta.b64 p, [%1], %2; selp.b32 %0,1,0,p; }" \
                 : "=r"(_d) : "r"(_m), "r"(_p) : "memory"); \
    if (!_d) { \
        asm volatile("{ .reg .pred P1; WL_%=: mbarrier.try_wait.parity.acquire.cta.shared::cta.b64 P1, [%0], %1, 0x989680; @P1 bra.uni WD_%=; bra.uni WL_%=; WD_%=: }" \
                     :: "r"(_m), "r"(_p) : "memory"); \
    } } while (0)

#define LDTM_X32(r, addr) \
    asm volatile("tcgen05.ld.sync.aligned.32x32b.x32.b32 " \
        "{%0,%1,%2,%3,%4,%5,%6,%7,%8,%9,%10,%11,%12,%13,%14,%15," \
        "%16,%17,%18,%19,%20,%21,%22,%23,%24,%25,%26,%27,%28,%29,%30,%31}, [%32];" \
        : "=r"((r)[0]),"=r"((r)[1]),"=r"((r)[2]),"=r"((r)[3]),"=r"((r)[4]),"=r"((r)[5]),"=r"((r)[6]),"=r"((r)[7]), \
          "=r"((r)[8]),"=r"((r)[9]),"=r"((r)[10]),"=r"((r)[11]),"=r"((r)[12]),"=r"((r)[13]),"=r"((r)[14]),"=r"((r)[15]), \
          "=r"((r)[16]),"=r"((r)[17]),"=r"((r)[18]),"=r"((r)[19]),"=r"((r)[20]),"=r"((r)[21]),"=r"((r)[22]),"=r"((r)[23]), \
          "=r"((r)[24]),"=r"((r)[25]),"=r"((r)[26]),"=r"((r)[27]),"=r"((r)[28]),"=r"((r)[29]),"=r"((r)[30]),"=r"((r)[31]) \
        : "r"(addr))

__device__ __forceinline__ void mma_f16_ss(uint32_t d, uint64_t a, uint64_t b,
                                           uint32_t idesc, uint32_t en) {
    asm volatile(
        "{\n\t.reg .pred p;\n\t"
        "setp.ne.u32 p, %5, 0;\n\t"
        "tcgen05.mma.cta_group::1.kind::f16 [%0], %1, %2, %3, {%4,%4,%4,%4}, p;\n\t}"
        :: "r"(d), "l"(a), "l"(b), "r"(idesc), "r"(0u), "r"(en) : "memory");
}

static constexpr uint64_t DESC_BASE =
    (uint64_t(2) << 61) | (uint64_t(1) << 46) | (uint64_t(64) << 32) | (uint64_t(1) << 16);
static constexpr uint32_t IDESC =
    (1u << 4) | (1u << 7) | (1u << 10) | ((128u / 8) << 17) | ((128u / 16) << 24);

__device__ __forceinline__ uint32_t tile_off(int row, int col) {
    uint32_t off = (uint32_t)((row >> 3) + ((col >> 6) << 4)) * 1024u
                 + (uint32_t)(row & 7) * 128u + (uint32_t)(col & 63) * 2u;
    return off ^ ((off >> 3) & 0x70);
}

__device__ __forceinline__ float fast_ex2(float x) {
    float r; asm("ex2.approx.f32 %0, %1;" : "=f"(r) : "f"(x)); return r;
}

// packed f32x2 helpers
#define PK2(d, lo, hi)  asm("mov.b64 %0, {%1,%2};" : "=l"(d) : "r"(__float_as_uint(lo)), "r"(__float_as_uint(hi)))
#define UPK2(lo, hi, s) asm("mov.b64 {%0,%1}, %2;" : "=r"(lo), "=r"(hi) : "l"(s))
#define ADD2(d, a, b)   asm("add.rn.f32x2 %0, %1, %2;" : "=l"(d) : "l"(a), "l"(b))
#define MUL2(d, a, b)   asm("mul.rn.f32x2 %0, %1, %2;" : "=l"(d) : "l"(a), "l"(b))
#define FMA2(d, a, b, c) asm("fma.rn.f32x2 %0, %1, %2, %3;" : "=l"(d) : "l"(a), "l"(b), "l"(c))
#endif  // HAS_TCGEN05

// ---------------------------------------------------------------------------
__global__ __launch_bounds__(256)
void k_convert(const float* __restrict__ f) {
    int idx = blockIdx.x * 256 + threadIdx.x;
    if (idx < NN * DD / 4) {
        float4 v = ((const float4*)f)[idx];
        __nv_bfloat16 h0 = __float2bfloat16(v.x), h1 = __float2bfloat16(v.y);
        __nv_bfloat16 h2 = __float2bfloat16(v.z), h3 = __float2bfloat16(v.w);
        __nv_bfloat162* hp = (__nv_bfloat162*)(g_hi + (size_t)idx * 4);
        __nv_bfloat162* lp = (__nv_bfloat162*)(g_lo + (size_t)idx * 4);
        hp[0] = __nv_bfloat162(h0, h1);
        hp[1] = __nv_bfloat162(h2, h3);
        lp[0] = __nv_bfloat162(__float2bfloat16(v.x - __bfloat162float(h0)),
                               __float2bfloat16(v.y - __bfloat162float(h1)));
        lp[1] = __nv_bfloat162(__float2bfloat16(v.z - __bfloat162float(h2)),
                               __float2bfloat16(v.w - __bfloat162float(h3)));
    }
}

// ---------------------------------------------------------------------------
// Persistent schedule: 148 CTAs, CTA c owns linear tiles [TTOT*c/148, TTOT*(c+1)/148)
// (i-major). Pipelined cp.async B (2 ahead), ping-pong TMEM, packed-f32x2
// epilogue accumulating Te,Te1,Td,Td1,Te2,Te21 per row (label-1-weighted trick).
// ---------------------------------------------------------------------------
__global__ __launch_bounds__(256, 1)
void k_tiles(const int* __restrict__ labels) {
#if HAS_TCGEN05
    extern __shared__ char smem[];
    const uint32_t sb = smem_u32(smem);
    const int tid = threadIdx.x;
    const int cta = blockIdx.x;
    float* labF = (float*)(smem + OFF_LABF);

    const int t0 = (TTOT * cta) / NCTA;
    const int t1 = (TTOT * (cta + 1)) / NCTA;
    const int len = t1 - t0;

    if (tid == 0) { MBAR_INIT(sb + OFF_MBAR0, 1); MBAR_INIT(sb + OFF_MBAR0 + 8, 1); }
    if (tid < 32) { TCG_ALLOC(sb + OFF_TMEM, 256); TCG_RELINQ(); }
    __syncthreads();
    uint32_t tmem;
    asm volatile("ld.shared.b32 %0, [%1];" : "=r"(tmem) : "r"(sb + OFF_TMEM));

    const int lrow = tid >> 1, lhalf = tid & 1;

#define LOADA(ii) do { \
        const uint4* _ah = (const uint4*)(g_hi + (size_t)((ii) * 128 + lrow) * DD + lhalf * 64); \
        const uint4* _al = (const uint4*)(g_lo + (size_t)((ii) * 128 + lrow) * DD + lhalf * 64); \
        _Pragma("unroll") \
        for (int _c = 0; _c < 8; _c++) { \
            uint32_t _o = tile_off(lrow, lhalf * 64 + _c * 8); \
            *(uint4*)(smem + SM_AHI + _o) = _ah[_c]; \
            *(uint4*)(smem + SM_ALO + _o) = _al[_c]; \
        } } while (0)

#define CPLOADB(k) do { \
        int _jb = ((t0 + (k)) & 63) * 128; \
        const char* _sh = (const char*)(g_hi + (size_t)(_jb + lrow) * DD + lhalf * 64); \
        const char* _sl = (const char*)(g_lo + (size_t)(_jb + lrow) * DD + lhalf * 64); \
        uint32_t _bb = sb + SM_B0 + ((k) & 1) * BSTRIDE; \
        _Pragma("unroll") \
        for (int _c = 0; _c < 8; _c++) { \
            uint32_t _o = tile_off(lrow, lhalf * 64 + _c * 8); \
            CP_ASYNC16(_bb + _o, _sh + _c * 16); \
            CP_ASYNC16(_bb + 32768 + _o, _sl + _c * 16); \
        } \
        CP_COMMIT(); \
    } while (0)

#define LABLOAD(k) do { \
        if (tid < 128) { \
            int _jb = ((t0 + (k)) & 63) * 128; \
            labF[((k) & 3) * 128 + tid] = (float)__ldg(&labels[_jb + tid]); \
        } } while (0)

#define ISSUE(k) do { \
        uint32_t _dtm = tmem + ((k) & 1) * 128; \
        uint32_t _bb = sb + SM_B0 + ((k) & 1) * BSTRIDE; \
        uint64_t _bH = DESC_BASE | ((uint64_t)(_bb >> 4) & 0x3FFF); \
        uint64_t _bL = DESC_BASE | ((uint64_t)((_bb + 32768) >> 4) & 0x3FFF); \
        uint64_t _aH = DESC_BASE | ((uint64_t)((sb + SM_AHI) >> 4) & 0x3FFF); \
        uint64_t _aL = DESC_BASE | ((uint64_t)((sb + SM_ALO) >> 4) & 0x3FFF); \
        const uint64_t _offs[8] = {0, 2, 4, 6, 1024, 1026, 1028, 1030}; \
        uint32_t _en = 0; \
        _Pragma("unroll") \
        for (int _k = 0; _k < 8; _k++) { mma_f16_ss(_dtm, _aH + _offs[_k], _bH + _offs[_k], IDESC, _en); _en = 1; } \
        _Pragma("unroll") \
        for (int _k = 0; _k < 8; _k++) mma_f16_ss(_dtm, _aH + _offs[_k], _bL + _offs[_k], IDESC, 1); \
        _Pragma("unroll") \
        for (int _k = 0; _k < 8; _k++) mma_f16_ss(_dtm, _aL + _offs[_k], _bH + _offs[_k], IDESC, 1); \
        TCG_COMMIT(sb + OFF_MBAR0 + ((k) & 1) * 8); \
    } while (0)

    int aI = t0 >> 6;
    LOADA(aI);
    CPLOADB(0); LABLOAD(0);
    CPLOADB(1); LABLOAD(1);
    CP_WAIT(1);
    __syncthreads();
    if (tid == 0) { FENCE_ASYNC_SHARED(); ISSUE(0); }

    // epilogue mapping
    const int lane = tid & 31;
    const int row = ((tid >> 5) & 3) * 32 + lane;
    const int colBase = (tid >> 7) * 64;
    const float C1 = 14.4269504089f;   // 10*log2(e)

    int epiI = aI;
    int gRow = epiI * 128 + row;
    unsigned long long Te = 0, Te1 = 0, Td = 0, Td1 = 0, Te2 = 0, Te21 = 0;

#define FLUSH() do { \
        uint32_t _l, _h; float _a, _b; \
        UPK2(_l, _h, Te);  _a = __uint_as_float(_l) + __uint_as_float(_h); atomicAdd(&g_Te[gRow], _a); \
        UPK2(_l, _h, Te1); _a = __uint_as_float(_l) + __uint_as_float(_h); atomicAdd(&g_Te1[gRow], _a); \
        UPK2(_l, _h, Td);  _a = __uint_as_float(_l) + __uint_as_float(_h); atomicAdd(&g_Td[gRow], _a); \
        UPK2(_l, _h, Td1); _b = __uint_as_float(_l) + __uint_as_float(_h); atomicAdd(&g_Td1[gRow], _b); \
        UPK2(_l, _h, Te2); _a = __uint_as_float(_l) + __uint_as_float(_h); atomicAdd(&g_Te2[gRow], _a); \
        UPK2(_l, _h, Te21);_a = __uint_as_float(_l) + __uint_as_float(_h); atomicAdd(&g_Te21[gRow], _a); \
    } while (0)

    for (int k = 0; k < len; k++) {
        MBAR_WAIT(sb + OFF_MBAR0 + (k & 1) * 8, (k >> 1) & 1);
        TCG_FENCE_AFTER();

        const bool pref = (k + 2 < len);
        if (pref) { CPLOADB(k + 2); LABLOAD(k + 2); }
        if (k + 1 < len) {
            int ni = (t0 + k + 1) >> 6;
            if (ni != aI) { LOADA(ni); aI = ni; }   // all MMAs <= k complete
            if (pref) CP_WAIT(1); else CP_WAIT(0);
            __syncthreads();
            if (tid == 0) { FENCE_ASYNC_SHARED(); ISSUE(k + 1); }
        }

        const int ei = (t0 + k) >> 6;
        if (ei != epiI) {
            FLUSH();
            Te = Te1 = Td = Td1 = Te2 = Te21 = 0;
            epiI = ei;
            gRow = epiI * 128 + row;
        }

        const int tj = (t0 + k) & 63;
        const uint32_t dtm = tmem + (k & 1) * 128 + colBase;

        uint32_t r0[32], r1[32];
        LDTM_X32(r0, dtm);
        LDTM_X32(r1, dtm + 32);
        TCG_WAIT_LD();

        const uint32_t labAddr = sb + OFF_LABF + (k & 3) * 512 + colBase * 4;
#pragma unroll
        for (int half = 0; half < 2; half++) {
            const uint32_t* rr = half ? r1 : r0;
            const uint32_t lA = labAddr + half * 128;
#pragma unroll
            for (int p = 0; p < 16; p++) {
                float d0 = __uint_as_float(rr[2 * p]);
                float d1 = __uint_as_float(rr[2 * p + 1]);
                float e0 = fast_ex2(fmaf(d0, C1, -C1));
                float e1 = fast_ex2(fmaf(d1, C1, -C1));
                unsigned long long pd, pe, pe2, pw;
                PK2(pd, d0, d1);
                PK2(pe, e0, e1);
                MUL2(pe2, pe, pe);
                asm("ld.shared.b64 %0, [%1];" : "=l"(pw) : "r"(lA + p * 8));
                ADD2(Td, Td, pd);
                ADD2(Te, Te, pe);
                ADD2(Te2, Te2, pe2);
                FMA2(Td1, pw, pd, Td1);
                FMA2(Te1, pw, pe, Te1);
                FMA2(Te21, pw, pe2, Te21);
            }
        }

        // diagonal capture: tile (ei, ei), thread owning col == row
        if (tj == ei && (row >> 6) == (tid >> 7)) {
            int c = row - colBase;
            float dv = __uint_as_float((c >= 32 ? r1 : r0)[c & 31]);
            g_dd[gRow] = dv;
            g_de[gRow] = fast_ex2(fmaf(dv, C1, -C1));
        }
        TCG_FENCE_BEFORE();
    }
    FLUSH();

    __syncthreads();
    if (tid == 0) { MBAR_INVAL(sb + OFF_MBAR0); MBAR_INVAL(sb + OFF_MBAR0 + 8); }
    __syncthreads();
    if (tid < 32) TCG_DEALLOC(tmem, 256);
#undef LOADA
#undef CPLOADB
#undef LABLOAD
#undef ISSUE
#undef FLUSH
#endif  // HAS_TCGEN05
}

// ---------------------------------------------------------------------------
// k_final: per-row reconstruction + mean.
//   same* = lab ? X1 : X - X1 ; pos stats = same - diag; neg = Te - sameE
//   cnt = lab ? n1-1 : NN-n1-1
//   sum_pos log(e^d+neg) ~= cnt*ln(neg) + S1/neg - S2/(2 neg^2)
// ---------------------------------------------------------------------------
__global__ __launch_bounds__(1024)
void k_final(const int* __restrict__ labels, float* __restrict__ out) {
    const int tid = threadIdx.x;
    __shared__ float sS[1024];
    __shared__ int sN[1024];

    int ln = 0;
#pragma unroll
    for (int it = 0; it < NN / 1024; it++) ln += labels[it * 1024 + tid];
    sN[tid] = ln;
    __syncthreads();
    for (int k = 512; k > 0; k >>= 1) {
        if (tid < k) sN[tid] += sN[tid + k];
        __syncthreads();
    }
    const int n1 = sN[0];

    float s = 0.0f;
#pragma unroll
    for (int it = 0; it < NN / 1024; it++) {
        int i = it * 1024 + tid;
        int lab = labels[i];
        float Te = g_Te[i], Te1 = g_Te1[i];
        float Td = g_Td[i], Td1 = g_Td1[i];
        float Te2 = g_Te2[i], Te21 = g_Te21[i];
        float sameE  = lab ? Te1  : Te  - Te1;
        float sameD  = lab ? Td1  : Td  - Td1;
        float sameE2 = lab ? Te21 : Te2 - Te21;
        float ed = g_de[i], dd = g_dd[i];
        float S1 = sameE - ed;
        float posDot = sameD - dd;
        float S2 = sameE2 - ed * ed;
        float neg = Te - sameE;
        float cnt = (float)(lab ? (n1 - 1) : (NN - n1 - 1));
        float posD = 10.0f * posDot - 10.0f * cnt;
        float inv = 1.0f / neg;
        float lsum = cnt * __logf(neg) + S1 * inv - 0.5f * S2 * inv * inv;
        s += (posD - lsum) / cnt;
    }
    sS[tid] = s;
    __syncthreads();
    for (int k = 512; k > 0; k >>= 1) {
        if (tid < k) sS[tid] += sS[tid + k];
        __syncthreads();
    }
    if (tid == 0) out[0] = -(0.1f / 0.07f) * sS[0] / (float)NN;
}

// ---------------------------------------------------------------------------
extern "C" void kernel_launch(void* const* d_in, const int* in_sizes, int n_in,
                              void* d_out, int out_size) {
    const float* feats = (const float*)d_in[0];
    const int* labels = (const int*)d_in[1];
    float* out = (float*)d_out;

    void* p;
    cudaGetSymbolAddress(&p, g_Te);   cudaMemsetAsync(p, 0, NN * sizeof(float));
    cudaGetSymbolAddress(&p, g_Te1);  cudaMemsetAsync(p, 0, NN * sizeof(float));
    cudaGetSymbolAddress(&p, g_Td);   cudaMemsetAsync(p, 0, NN * sizeof(float));
    cudaGetSymbolAddress(&p, g_Td1);  cudaMemsetAsync(p, 0, NN * sizeof(float));
    cudaGetSymbolAddress(&p, g_Te2);  cudaMemsetAsync(p, 0, NN * sizeof(float));
    cudaGetSymbolAddress(&p, g_Te21); cudaMemsetAsync(p, 0, NN * sizeof(float));

    cudaFuncSetAttribute(k_tiles, cudaFuncAttributeMaxDynamicSharedMemorySize, SM_TOTAL);

    k_convert<<<(NN * DD / 4 + 255) / 256, 256>>>(feats);
    k_tiles<<<NCTA, 256, SM_TOTAL>>>(labels);
    k_final<<<1, 1024>>>(labels, out);
}

// round 11
// speedup vs baseline: 7.1356x; 1.4364x over previous
#include <cuda_runtime.h>
#include <cuda_bf16.h>
#include <cstdint>
#include <math.h>

#define NN 8192
#define DD 128
#define NTILE 64
#define TTOT (NTILE * NTILE)
#define NCTA 148
#define NTHR 512

#if defined(__CUDA_ARCH__) && \
    (defined(__CUDA_ARCH_FEAT_SM103_ALL) || defined(__CUDA_ARCH_FEAT_SM100_ALL) || \
     defined(__CUDA_ARCH_SPECIFIC__) || defined(__CUDA_ARCH_FAMILY_SPECIFIC__))
#define HAS_TCGEN05 1
#else
#define HAS_TCGEN05 0
#endif

// scale = sqrt(10/ln2) so the MMA produces z = (10*log2 e) * dot directly
#define FSCALE 3.7982826f
#define C1F 14.4269504f          // 10*log2(e)
#define LN2F 0.69314718f

// ---------------- scratch (static device memory; no runtime alloc) ----------
__device__ __nv_bfloat16 g_hi[(size_t)NN * DD];
__device__ __nv_bfloat16 g_lo[(size_t)NN * DD];
__device__ float g_Te[NN], g_Te1[NN], g_Td[NN], g_Td1[NN];
__device__ float g_de[NN], g_dd[NN];
__device__ float g_part[8];

// ---------------- SMEM layout (tile bases 1024-aligned) ---------------------
#define OFF_TMEM 0
#define OFF_MBAR0 8
#define OFF_LABF 1024          // float[4][128] = 2 KB
#define SM_AHI 4096
#define SM_ALO (SM_AHI + 32768)
#define SM_B0  (SM_ALO + 32768)
#define BSTRIDE 65536
#define SM_TOTAL (SM_B0 + 2 * BSTRIDE)   // 200704 B

#if HAS_TCGEN05
__device__ __forceinline__ uint32_t smem_u32(const void* p) {
    uint32_t a;
    asm("{ .reg .u64 t; cvta.to.shared.u64 t, %1; cvt.u32.u64 %0, t; }" : "=r"(a) : "l"(p));
    return a;
}
#define TCG_ALLOC(sm, n) asm volatile("tcgen05.alloc.cta_group::1.sync.aligned.shared::cta.b32 [%0], %1;" :: "r"(sm), "r"(n) : "memory")
#define TCG_DEALLOC(t, n) asm volatile("tcgen05.dealloc.cta_group::1.sync.aligned.b32 %0, %1;" :: "r"(t), "r"(n))
#define TCG_RELINQ() asm volatile("tcgen05.relinquish_alloc_permit.cta_group::1.sync.aligned;")
#define TCG_COMMIT(mb) asm volatile("tcgen05.commit.cta_group::1.mbarrier::arrive::one.shared::cluster.b64 [%0];" :: "r"(mb) : "memory")
#define TCG_WAIT_LD() asm volatile("tcgen05.wait::ld.sync.aligned;" ::: "memory")
#define TCG_FENCE_BEFORE() asm volatile("tcgen05.fence::before_thread_sync;" ::: "memory")
#define TCG_FENCE_AFTER() asm volatile("tcgen05.fence::after_thread_sync;" ::: "memory")
#define FENCE_ASYNC_SHARED() asm volatile("fence.proxy.async.shared::cta;" ::: "memory")
#define MBAR_INIT(mb, c) asm volatile("mbarrier.init.shared.b64 [%0], %1;" :: "r"(mb), "r"(c) : "memory")
#define MBAR_INVAL(mb) asm volatile("mbarrier.inval.shared.b64 [%0];" :: "r"(mb) : "memory")
#define CP_ASYNC16(dst, src) asm volatile("cp.async.cg.shared.global [%0], [%1], 16;" :: "r"(dst), "l"(src) : "memory")
#define CP_COMMIT() asm volatile("cp.async.commit_group;" ::: "memory")
#define CP_WAIT(n) asm volatile("cp.async.wait_group %0;" :: "n"(n) : "memory")

#define MBAR_WAIT(mb, ph) do { \
    uint32_t _m = (mb); uint32_t _p = (ph); uint32_t _d; \
    asm volatile("{ .reg .pred p; mbarrier.try_wait.parity.acquire.cta.shared::cta.b64 p, [%1], %2; selp.b32 %0,1,0,p; }" \
                 : "=r"(_d) : "r"(_m), "r"(_p) : "memory"); \
    if (!_d) { \
        asm volatile("{ .reg .pred P1; WL_%=: mbarrier.try_wait.parity.acquire.cta.shared::cta.b64 P1, [%0], %1, 0x989680; @P1 bra.uni WD_%=; bra.uni WL_%=; WD_%=: }" \
                     :: "r"(_m), "r"(_p) : "memory"); \
    } } while (0)

#define LDTM_X32(r, addr) \
    asm volatile("tcgen05.ld.sync.aligned.32x32b.x32.b32 " \
        "{%0,%1,%2,%3,%4,%5,%6,%7,%8,%9,%10,%11,%12,%13,%14,%15," \
        "%16,%17,%18,%19,%20,%21,%22,%23,%24,%25,%26,%27,%28,%29,%30,%31}, [%32];" \
        : "=r"((r)[0]),"=r"((r)[1]),"=r"((r)[2]),"=r"((r)[3]),"=r"((r)[4]),"=r"((r)[5]),"=r"((r)[6]),"=r"((r)[7]), \
          "=r"((r)[8]),"=r"((r)[9]),"=r"((r)[10]),"=r"((r)[11]),"=r"((r)[12]),"=r"((r)[13]),"=r"((r)[14]),"=r"((r)[15]), \
          "=r"((r)[16]),"=r"((r)[17]),"=r"((r)[18]),"=r"((r)[19]),"=r"((r)[20]),"=r"((r)[21]),"=r"((r)[22]),"=r"((r)[23]), \
          "=r"((r)[24]),"=r"((r)[25]),"=r"((r)[26]),"=r"((r)[27]),"=r"((r)[28]),"=r"((r)[29]),"=r"((r)[30]),"=r"((r)[31]) \
        : "r"(addr))

__device__ __forceinline__ void mma_f16_ss(uint32_t d, uint64_t a, uint64_t b,
                                           uint32_t idesc, uint32_t en) {
    asm volatile(
        "{\n\t.reg .pred p;\n\t"
        "setp.ne.u32 p, %5, 0;\n\t"
        "tcgen05.mma.cta_group::1.kind::f16 [%0], %1, %2, %3, {%4,%4,%4,%4}, p;\n\t}"
        :: "r"(d), "l"(a), "l"(b), "r"(idesc), "r"(0u), "r"(en) : "memory");
}

static constexpr uint64_t DESC_BASE =
    (uint64_t(2) << 61) | (uint64_t(1) << 46) | (uint64_t(64) << 32) | (uint64_t(1) << 16);
static constexpr uint32_t IDESC =
    (1u << 4) | (1u << 7) | (1u << 10) | ((128u / 8) << 17) | ((128u / 16) << 24);

__device__ __forceinline__ uint32_t tile_off(int row, int col) {
    uint32_t off = (uint32_t)((row >> 3) + ((col >> 6) << 4)) * 1024u
                 + (uint32_t)(row & 7) * 128u + (uint32_t)(col & 63) * 2u;
    return off ^ ((off >> 3) & 0x70);
}

__device__ __forceinline__ float fast_ex2(float x) {
    float r; asm("ex2.approx.f32 %0, %1;" : "=f"(r) : "f"(x)); return r;
}

#define PK2(d, lo, hi)  asm("mov.b64 %0, {%1,%2};" : "=l"(d) : "r"(__float_as_uint(lo)), "r"(__float_as_uint(hi)))
#define UPK2(lo, hi, s) asm("mov.b64 {%0,%1}, %2;" : "=r"(lo), "=r"(hi) : "l"(s))
#define ADD2(d, a, b)   asm("add.rn.f32x2 %0, %1, %2;" : "=l"(d) : "l"(a), "l"(b))
#define FMA2(d, a, b, c) asm("fma.rn.f32x2 %0, %1, %2, %3;" : "=l"(d) : "l"(a), "l"(b), "l"(c))
#endif  // HAS_TCGEN05

// ---------------------------------------------------------------------------
// Split (FSCALE * x) into bf16 hi/lo
// ---------------------------------------------------------------------------
__global__ __launch_bounds__(256)
void k_convert(const float* __restrict__ f) {
    int idx = blockIdx.x * 256 + threadIdx.x;
    if (idx < NN * DD / 4) {
        float4 v = ((const float4*)f)[idx];
        v.x *= FSCALE; v.y *= FSCALE; v.z *= FSCALE; v.w *= FSCALE;
        __nv_bfloat16 h0 = __float2bfloat16(v.x), h1 = __float2bfloat16(v.y);
        __nv_bfloat16 h2 = __float2bfloat16(v.z), h3 = __float2bfloat16(v.w);
        __nv_bfloat162* hp = (__nv_bfloat162*)(g_hi + (size_t)idx * 4);
        __nv_bfloat162* lp = (__nv_bfloat162*)(g_lo + (size_t)idx * 4);
        hp[0] = __nv_bfloat162(h0, h1);
        hp[1] = __nv_bfloat162(h2, h3);
        lp[0] = __nv_bfloat162(__float2bfloat16(v.x - __bfloat162float(h0)),
                               __float2bfloat16(v.y - __bfloat162float(h1)));
        lp[1] = __nv_bfloat162(__float2bfloat16(v.z - __bfloat162float(h2)),
                               __float2bfloat16(v.w - __bfloat162float(h3)));
    }
}

// ---------------------------------------------------------------------------
// Persistent 148-CTA schedule, 512 threads, cp.async 2-ahead, ping-pong TMEM.
// MMA gives z = C1*dot. Accumulates Te,Te1,Td,Td1 per row (label-1 trick).
// ---------------------------------------------------------------------------
__global__ __launch_bounds__(NTHR, 1)
void k_tiles(const int* __restrict__ labels) {
#if HAS_TCGEN05
    extern __shared__ char smem[];
    const uint32_t sb = smem_u32(smem);
    const int tid = threadIdx.x;
    const int cta = blockIdx.x;

    const int t0 = (TTOT * cta) / NCTA;
    const int t1 = (TTOT * (cta + 1)) / NCTA;
    const int len = t1 - t0;

    if (tid == 0) { MBAR_INIT(sb + OFF_MBAR0, 1); MBAR_INIT(sb + OFF_MBAR0 + 8, 1); }
    if (tid < 32) { TCG_ALLOC(sb + OFF_TMEM, 256); TCG_RELINQ(); }
    __syncthreads();
    uint32_t tmem;
    asm volatile("ld.shared.b32 %0, [%1];" : "=r"(tmem) : "r"(sb + OFF_TMEM));

    const int lrow = tid >> 2, lq = tid & 3;   // loader: row 0..127, col quarter

#define LOADA(ii) do { \
        const uint4* _ah = (const uint4*)(g_hi + (size_t)((ii) * 128 + lrow) * DD + lq * 32); \
        const uint4* _al = (const uint4*)(g_lo + (size_t)((ii) * 128 + lrow) * DD + lq * 32); \
        _Pragma("unroll") \
        for (int _c = 0; _c < 4; _c++) { \
            uint32_t _o = tile_off(lrow, lq * 32 + _c * 8); \
            *(uint4*)(smem + SM_AHI + _o) = _ah[_c]; \
            *(uint4*)(smem + SM_ALO + _o) = _al[_c]; \
        } } while (0)

#define CPLOADB(k) do { \
        int _jb = ((t0 + (k)) & 63) * 128; \
        const char* _sh = (const char*)(g_hi + (size_t)(_jb + lrow) * DD + lq * 32); \
        const char* _sl = (const char*)(g_lo + (size_t)(_jb + lrow) * DD + lq * 32); \
        uint32_t _bb = sb + SM_B0 + ((k) & 1) * BSTRIDE; \
        _Pragma("unroll") \
        for (int _c = 0; _c < 4; _c++) { \
            uint32_t _o = tile_off(lrow, lq * 32 + _c * 8); \
            CP_ASYNC16(_bb + _o, _sh + _c * 16); \
            CP_ASYNC16(_bb + 32768 + _o, _sl + _c * 16); \
        } \
        CP_COMMIT(); \
    } while (0)

#define LABLOAD(k) do { \
        if (tid < 128) { \
            int _jb = ((t0 + (k)) & 63) * 128; \
            ((float*)(smem + OFF_LABF))[((k) & 3) * 128 + tid] = (float)__ldg(&labels[_jb + tid]); \
        } } while (0)

#define ISSUE(k) do { \
        uint32_t _dtm = tmem + ((k) & 1) * 128; \
        uint32_t _bb = sb + SM_B0 + ((k) & 1) * BSTRIDE; \
        uint64_t _bH = DESC_BASE | ((uint64_t)(_bb >> 4) & 0x3FFF); \
        uint64_t _bL = DESC_BASE | ((uint64_t)((_bb + 32768) >> 4) & 0x3FFF); \
        uint64_t _aH = DESC_BASE | ((uint64_t)((sb + SM_AHI) >> 4) & 0x3FFF); \
        uint64_t _aL = DESC_BASE | ((uint64_t)((sb + SM_ALO) >> 4) & 0x3FFF); \
        const uint64_t _offs[8] = {0, 2, 4, 6, 1024, 1026, 1028, 1030}; \
        uint32_t _en = 0; \
        _Pragma("unroll") \
        for (int _k = 0; _k < 8; _k++) { mma_f16_ss(_dtm, _aH + _offs[_k], _bH + _offs[_k], IDESC, _en); _en = 1; } \
        _Pragma("unroll") \
        for (int _k = 0; _k < 8; _k++) mma_f16_ss(_dtm, _aH + _offs[_k], _bL + _offs[_k], IDESC, 1); \
        _Pragma("unroll") \
        for (int _k = 0; _k < 8; _k++) mma_f16_ss(_dtm, _aL + _offs[_k], _bH + _offs[_k], IDESC, 1); \
        TCG_COMMIT(sb + OFF_MBAR0 + ((k) & 1) * 8); \
    } while (0)

    int aI = t0 >> 6;
    LOADA(aI);
    CPLOADB(0); LABLOAD(0);
    CPLOADB(1); LABLOAD(1);
    CP_WAIT(1);
    __syncthreads();
    if (tid == 0) { FENCE_ASYNC_SHARED(); ISSUE(0); }

    // epilogue mapping: row = tid%128, col quarter = tid/128 (32 cols/thread)
    const int row = tid & 127;
    const int colBase = (tid >> 7) * 32;

    int epiI = aI;
    int gRow = epiI * 128 + row;
    unsigned long long Te = 0, Te1 = 0, Td = 0, Td1 = 0;

#define FLUSH() do { \
        uint32_t _l, _h; float _a; \
        UPK2(_l, _h, Te);  _a = __uint_as_float(_l) + __uint_as_float(_h); atomicAdd(&g_Te[gRow], _a); \
        UPK2(_l, _h, Te1); _a = __uint_as_float(_l) + __uint_as_float(_h); atomicAdd(&g_Te1[gRow], _a); \
        UPK2(_l, _h, Td);  _a = __uint_as_float(_l) + __uint_as_float(_h); atomicAdd(&g_Td[gRow], _a); \
        UPK2(_l, _h, Td1); _a = __uint_as_float(_l) + __uint_as_float(_h); atomicAdd(&g_Td1[gRow], _a); \
    } while (0)

    for (int k = 0; k < len; k++) {
        MBAR_WAIT(sb + OFF_MBAR0 + (k & 1) * 8, (k >> 1) & 1);
        TCG_FENCE_AFTER();

        const bool pref = (k + 2 < len);
        if (pref) { CPLOADB(k + 2); LABLOAD(k + 2); }
        if (k + 1 < len) {
            int ni = (t0 + k + 1) >> 6;
            if (ni != aI) { LOADA(ni); aI = ni; }
            if (pref) CP_WAIT(1); else CP_WAIT(0);
            __syncthreads();
            if (tid == 0) { FENCE_ASYNC_SHARED(); ISSUE(k + 1); }
        }

        const int ei = (t0 + k) >> 6;
        if (ei != epiI) {
            FLUSH();
            Te = Te1 = Td = Td1 = 0;
            epiI = ei;
            gRow = epiI * 128 + row;
        }

        const int tj = (t0 + k) & 63;
        uint32_t r0[32];
        LDTM_X32(r0, tmem + (k & 1) * 128 + colBase);
        TCG_WAIT_LD();

        const uint32_t lA = sb + OFF_LABF + (k & 3) * 512 + colBase * 4;
#pragma unroll
        for (int p = 0; p < 16; p++) {
            float z0 = __uint_as_float(r0[2 * p]);
            float z1 = __uint_as_float(r0[2 * p + 1]);
            float e0 = fast_ex2(z0 - C1F);
            float e1 = fast_ex2(z1 - C1F);
            unsigned long long pz, pe, pw;
            PK2(pz, z0, z1);
            PK2(pe, e0, e1);
            asm("ld.shared.b64 %0, [%1];" : "=l"(pw) : "r"(lA + p * 8));
            ADD2(Td, Td, pz);
            ADD2(Te, Te, pe);
            FMA2(Td1, pw, pz, Td1);
            FMA2(Te1, pw, pe, Te1);
        }

        // diagonal capture (tile (ei,ei), thread owning col == row)
        if (tj == ei && (row >> 5) == (tid >> 7)) {
            float zv = __uint_as_float(r0[row & 31]);
            g_dd[gRow] = zv;
            g_de[gRow] = fast_ex2(zv - C1F);
        }
        TCG_FENCE_BEFORE();
    }
    FLUSH();

    __syncthreads();
    if (tid == 0) { MBAR_INVAL(sb + OFF_MBAR0); MBAR_INVAL(sb + OFF_MBAR0 + 8); }
    __syncthreads();
    if (tid < 32) TCG_DEALLOC(tmem, 256);
#undef LOADA
#undef CPLOADB
#undef LABLOAD
#undef ISSUE
#undef FLUSH
#endif  // HAS_TCGEN05
}

// ---------------------------------------------------------------------------
// k_final1 (8 CTAs): per-row reconstruction, partial sums. k_final2: combine.
//   sameE = lab? Te1 : Te-Te1 ; posZ = (lab? Td1 : Td-Td1) - dd ; S1 = sameE - de
//   neg = Te - sameE ; cnt = lab? n1-1 : NN-n1-1
//   posD = ln2*posZ - 10*cnt ; lsum = cnt*ln(neg) + S1/neg
// ---------------------------------------------------------------------------
__global__ __launch_bounds__(1024)
void k_final1(const int* __restrict__ labels) {
    const int tid = threadIdx.x;
    __shared__ int sN[1024];
    __shared__ float sS[1024];

    int ln = 0;
#pragma unroll
    for (int it = 0; it < NN / 1024; it++) ln += labels[it * 1024 + tid];
    sN[tid] = ln;
    __syncthreads();
    for (int k = 512; k > 0; k >>= 1) {
        if (tid < k) sN[tid] += sN[tid + k];
        __syncthreads();
    }
    const int n1 = sN[0];

    const int i = blockIdx.x * 1024 + tid;
    int lab = labels[i];
    float Te = g_Te[i], Te1 = g_Te1[i], Td = g_Td[i], Td1 = g_Td1[i];
    float sameE = lab ? Te1 : Te - Te1;
    float sameZ = lab ? Td1 : Td - Td1;
    float S1 = sameE - g_de[i];
    float posZ = sameZ - g_dd[i];
    float neg = Te - sameE;
    float cnt = (float)(lab ? (n1 - 1) : (NN - n1 - 1));
    float posD = LN2F * posZ - 10.0f * cnt;
    float lsum = cnt * __logf(neg) + S1 / neg;
    sS[tid] = (posD - lsum) / cnt;
    __syncthreads();
    for (int k = 512; k > 0; k >>= 1) {
        if (tid < k) sS[tid] += sS[tid + k];
        __syncthreads();
    }
    if (tid == 0) g_part[blockIdx.x] = sS[0];
}

__global__ void k_final2(float* __restrict__ out) {
    float s = 0.0f;
#pragma unroll
    for (int b = 0; b < 8; b++) s += g_part[b];
    out[0] = -(0.1f / 0.07f) * s / (float)NN;
}

// ---------------------------------------------------------------------------
extern "C" void kernel_launch(void* const* d_in, const int* in_sizes, int n_in,
                              void* d_out, int out_size) {
    const float* feats = (const float*)d_in[0];
    const int* labels = (const int*)d_in[1];
    float* out = (float*)d_out;

    void* p;
    cudaGetSymbolAddress(&p, g_Te);  cudaMemsetAsync(p, 0, NN * sizeof(float));
    cudaGetSymbolAddress(&p, g_Te1); cudaMemsetAsync(p, 0, NN * sizeof(float));
    cudaGetSymbolAddress(&p, g_Td);  cudaMemsetAsync(p, 0, NN * sizeof(float));
    cudaGetSymbolAddress(&p, g_Td1); cudaMemsetAsync(p, 0, NN * sizeof(float));

    cudaFuncSetAttribute(k_tiles, cudaFuncAttributeMaxDynamicSharedMemorySize, SM_TOTAL);

    k_convert<<<(NN * DD / 4 + 255) / 256, 256>>>(feats);
    k_tiles<<<NCTA, NTHR, SM_TOTAL>>>(labels);
    k_final1<<<8, 1024>>>(labels);
    k_final2<<<1, 1>>>(out);
}